// round 1
// baseline (speedup 1.0000x reference)
#include <cuda_runtime.h>
#include <cmath>
#include <vector>
#include <complex>

// ---------------- problem constants ----------------
#define NE   10          // experts
#define LF   20          // LMAX filter length (padded)
#define NB   32          // batch
#define NW   64          // width (channels)
#define NS   1024        // signal length
#define NM   64          // modes (level-4 coeff length)
#define NHID 4
#define NROW (NB*NW)     // 2048
#define NCOL (NE*2*NM)   // 1280

// ---------------- device scratch (no allocations allowed) ----------------
__device__ float g_bufA [NROW*NS];
__device__ float g_bufB [NROW*NS];
__device__ float g_corr [NROW*NS];
__device__ float g_coef [NROW*NCOL];
__device__ float g_delta[NROW*NCOL];
__device__ float g_S    [NS*NCOL];     // synthesis bases: [x][col], col=(e*2+t)*64+m
__device__ float g_xf   [NROW];
__device__ float g_lam  [NHID*NB*NE];
__device__ float g_A2   [NW*2];
__device__ float g_Bc   [NW];

struct Filters { float f[NE][2][LF]; };   // [expert][h/g][tap], passed by value

__device__ __forceinline__ float mishf(float x){
    float sp = (x > 20.f) ? x : log1pf(expf(x));
    return x * tanhf(sp);
}

// ---------------- build synthesis matrix columns ----------------
// One block per (e, t, m): cascade unit coeff vector 64->128->256->512->1024.
// out[x] = sum_j cur[j] * f[(x-2j) mod n_out], restricted to filter support:
// j = floor(x/2)-u (mod n_in), tap = (x&1)+2u, u=0..9.
__global__ __launch_bounds__(128) void build_syn_kernel(Filters F){
    __shared__ float b0[NS], b1[NS];
    int bid = blockIdx.x;
    int m = bid & 63, tt = (bid>>6)&1, e = bid>>7;
    int t = threadIdx.x;
    float* cur = b0; float* nxt = b1;
    for (int i=t;i<64;i+=128) cur[i] = (i==m)?1.f:0.f;
    __syncthreads();
    int n_in = 64;
    #pragma unroll
    for (int s=0;s<4;s++){
        int n_out = n_in<<1;
        const float* f = (s==0 && tt==1) ? F.f[e][1] : F.f[e][0];
        for (int x=t;x<n_out;x+=128){
            int j0 = x>>1, par = x&1;
            float acc = 0.f;
            #pragma unroll
            for (int u=0;u<10;u++){
                int j = j0-u; if (j<0) j += n_in;
                acc += cur[j]*f[par+2*u];
            }
            nxt[x]=acc;
        }
        __syncthreads();
        float* tp=cur; cur=nxt; nxt=tp;
        n_in = n_out;
    }
    int col = (e*2+tt)*64+m;
    for (int x=t;x<NS;x+=128) g_S[x*NCOL+col] = cur[x];
}

// ---------------- lift: h = fc1(fc0([x;grid])) ----------------
__global__ void prep_lift_kernel(const float* __restrict__ fc0_w, const float* __restrict__ fc0_b,
                                 const float* __restrict__ fc1_w, const float* __restrict__ fc1_b){
    int c = threadIdx.x;
    if (c >= NW) return;
    float a0=0.f,a1=0.f,bb=0.f;
    for (int k=0;k<NW;k++){
        float w = fc1_w[c*NW+k];
        a0 += w*fc0_w[k*2+0];
        a1 += w*fc0_w[k*2+1];
        bb += w*fc0_b[k];
    }
    g_A2[c*2]=a0; g_A2[c*2+1]=a1; g_Bc[c]=bb+fc1_b[c];
}

__global__ __launch_bounds__(256) void lift_kernel(const float* __restrict__ x){
    int idx = blockIdx.x*256 + threadIdx.x;
    if (idx >= NROW*NS) return;
    int xp = idx & (NS-1);
    int c  = (idx>>10)&63;
    int b  = idx>>16;
    float xv = x[b*NS+xp];
    float gv = (float)xp*(1.f/1023.f);
    g_bufA[idx] = g_A2[c*2]*xv + g_A2[c*2+1]*gv + g_Bc[c];
}

// ---------------- xf = mean over positions ----------------
__global__ __launch_bounds__(256) void xf_kernel(const float* __restrict__ h){
    __shared__ float red[256];
    int r = blockIdx.x, t = threadIdx.x;
    float s = 0.f;
    for (int xp=t; xp<NS; xp+=256) s += h[r*NS+xp];
    red[t]=s; __syncthreads();
    for (int o=128;o;o>>=1){ if (t<o) red[t]+=red[t+o]; __syncthreads(); }
    if (t==0) g_xf[r] = red[0]*(1.f/1024.f);
}

// ---------------- gates: softmax over experts per (hd, b) ----------------
__global__ __launch_bounds__(256) void gate_kernel(const float* __restrict__ label,
        const float* __restrict__ wl, const float* __restrict__ bl,
        const float* __restrict__ wg, const float* __restrict__ bg){
    __shared__ float s_lf[NHID][32];
    __shared__ float s_logit[NHID][NB][NE];
    __shared__ float s_xf[NB][NW];
    __shared__ float s_labsum;
    int t = threadIdx.x;
    if (t==0){ float s=0.f; for(int l=0;l<10;l++) s+=label[l]; s_labsum=s; }
    for (int idx=t; idx<NB*NW; idx+=256) s_xf[idx>>6][idx&63] = g_xf[idx];
    __syncthreads();
    if (t < 128){
        int hd=t>>5, o=t&31;
        float s=0.f;
        for (int c=0;c<NW;c++) s += wl[(hd*32+o)*NW+c];
        s_lf[hd][o] = s*s_labsum*0.1f + bl[hd*32+o];
    }
    __syncthreads();
    for (int idx=t; idx<NHID*NB*NE; idx+=256){
        int hd = idx/(NB*NE); int r = idx%(NB*NE); int b=r/NE, e=r%NE;
        const float* w = &wg[(hd*NE+e)*96];
        float s = bg[hd*NE+e];
        for (int c=0;c<NW;c++) s += s_xf[b][c]*w[c];
        for (int o=0;o<32;o++)  s += s_lf[hd][o]*w[64+o];
        s_logit[hd][b][e]=s;
    }
    __syncthreads();
    if (t < 128){
        int hd=t>>5, b=t&31;
        float mx=-1e30f;
        for (int e=0;e<NE;e++) mx = fmaxf(mx, s_logit[hd][b][e]);
        float ex[NE]; float sum=0.f;
        for (int e=0;e<NE;e++){ ex[e]=expf(s_logit[hd][b][e]-mx); sum+=ex[e]; }
        float inv = 1.f/sum;
        for (int e=0;e<NE;e++) g_lam[(hd*NB+b)*NE+e] = ex[e]*inv;
    }
}

// ---------------- SGEMM: 128x128x8 tiles, 8x8 per thread ----------------
// TB=0: C[M][N] = A[M][K] * B[K][N]   (both row-major)
// TB=1: C[M][N] = A[M][K] * B[N][K]^T (B row-major N x K)
template<int TB>
__global__ __launch_bounds__(256) void sgemm_kernel(
        const float* __restrict__ A, const float* __restrict__ B,
        float* __restrict__ C, int M, int N, int K){
    __shared__ float As[8][128];
    __shared__ float Bs[8][128];
    int t = threadIdx.x;
    int row0 = blockIdx.y * 128;
    int col0 = blockIdx.x * 128;
    int ar = t >> 1;          int ak  = (t & 1) * 4;
    int bk = t >> 5;          int bn  = (t & 31) * 4;
    int br = t >> 1;          int bk4 = (t & 1) * 4;
    int ty = t >> 4, tx = t & 15;
    float acc[8][8];
    #pragma unroll
    for (int i=0;i<8;i++)
        #pragma unroll
        for (int j=0;j<8;j++) acc[i][j]=0.f;

    for (int k0=0; k0<K; k0+=8){
        float4 av = *(const float4*)&A[(row0+ar)*K + k0 + ak];
        As[ak+0][ar]=av.x; As[ak+1][ar]=av.y; As[ak+2][ar]=av.z; As[ak+3][ar]=av.w;
        if (TB == 0){
            float4 bv = *(const float4*)&B[(k0+bk)*N + col0 + bn];
            *(float4*)&Bs[bk][bn] = bv;
        } else {
            float4 bv = *(const float4*)&B[(col0+br)*K + k0 + bk4];
            Bs[bk4+0][br]=bv.x; Bs[bk4+1][br]=bv.y; Bs[bk4+2][br]=bv.z; Bs[bk4+3][br]=bv.w;
        }
        __syncthreads();
        #pragma unroll
        for (int kk=0;kk<8;kk++){
            float a[8], b[8];
            #pragma unroll
            for (int i=0;i<8;i++) a[i] = As[kk][ty*8+i];
            #pragma unroll
            for (int j=0;j<8;j++) b[j] = Bs[kk][tx*8+j];
            #pragma unroll
            for (int i=0;i<8;i++)
                #pragma unroll
                for (int j=0;j<8;j++)
                    acc[i][j] += a[i]*b[j];
        }
        __syncthreads();
    }
    #pragma unroll
    for (int i=0;i<8;i++){
        float* cp = &C[(row0+ty*8+i)*N + col0 + tx*8];
        *(float4*)&cp[0] = make_float4(acc[i][0],acc[i][1],acc[i][2],acc[i][3]);
        *(float4*)&cp[4] = make_float4(acc[i][4],acc[i][5],acc[i][6],acc[i][7]);
    }
}

// ---------------- per-(expert,mode) channel mix: delta = lam*(W^T a - a) ----------------
__global__ __launch_bounds__(256) void mix_kernel(const float* __restrict__ ew1,
                                                  const float* __restrict__ ew2, int hd){
    __shared__ float sC[NROW];       // a4 (or d4) column: all (b,c)
    __shared__ float sW[NW*NW];      // w[i][o] at this mode
    int m = blockIdx.x, e = blockIdx.y, t = threadIdx.x;
    int wbase = (hd*NE+e)*NW*NW*NM + m;
    #pragma unroll
    for (int tt=0; tt<2; tt++){
        const float* W = tt ? ew2 : ew1;
        int col = (e*2+tt)*NM + m;
        __syncthreads();
        for (int i=t;i<NROW;i+=256) sC[i] = g_coef[i*NCOL + col];
        for (int i=t;i<NW*NW;i+=256) sW[i] = W[wbase + i*NM];
        __syncthreads();
        for (int oi=t; oi<NROW; oi+=256){
            int b = oi>>6, o = oi&63;
            float accv = -sC[oi];
            const float* cb = &sC[b*NW];
            #pragma unroll 8
            for (int i=0;i<NW;i++) accv += cb[i]*sW[i*NW+o];
            float l = g_lam[(hd*NB+b)*NE+e];
            g_delta[oi*NCOL + col] = accv*l;
        }
    }
}

// ---------------- combine: h_out = mish(h + corr + W h + b) ----------------
__global__ __launch_bounds__(256) void combine_kernel(const float* __restrict__ hin,
        const float* __restrict__ corr, const float* __restrict__ ww,
        const float* __restrict__ wb, float* __restrict__ hout, int hd){
    __shared__ float sH[NW][65];
    __shared__ float sW[NW][NW];
    int b = blockIdx.y, x0 = blockIdx.x*64, t = threadIdx.x;
    for (int idx=t; idx<NW*64; idx+=256){
        int c=idx>>6, xx=idx&63;
        sH[c][xx] = hin[(b*NW+c)*NS + x0+xx];
    }
    for (int idx=t; idx<NW*NW; idx+=256) sW[idx>>6][idx&63] = ww[hd*NW*NW+idx];
    __syncthreads();
    for (int idx=t; idx<NW*64; idx+=256){
        int c=idx>>6, xx=idx&63;
        float accv = wb[hd*NW+c];
        #pragma unroll 8
        for (int k=0;k<NW;k++) accv += sW[c][k]*sH[k][xx];
        int gi = (b*NW+c)*NS + x0+xx;
        float pre = sH[c][xx] + corr[gi] + accv;
        hout[gi] = mishf(pre);
    }
}

// ---------------- head: out = fc3(mish(fc2(h))) ----------------
__global__ __launch_bounds__(256) void head_kernel(const float* __restrict__ hin,
        const float* __restrict__ fc2_w, const float* __restrict__ fc2_b,
        const float* __restrict__ fc3_w, const float* __restrict__ fc3_b,
        float* __restrict__ out){
    __shared__ float sWT[NW*128];    // [k][j]
    __shared__ float sH[8][NW];
    __shared__ float sb2[128], sw3[128];
    int b = blockIdx.y, x0 = blockIdx.x*8, t = threadIdx.x;
    for (int idx=t; idx<128*NW; idx+=256){
        int j=idx>>6, k=idx&63;
        sWT[k*128+j] = fc2_w[idx];
    }
    if (t<128){ sb2[t]=fc2_b[t]; sw3[t]=fc3_w[t]; }
    for (int idx=t; idx<8*NW; idx+=256){
        int c = idx>>3, xx = idx&7;
        sH[xx][c] = hin[(b*NW+c)*NS + x0+xx];
    }
    __syncthreads();
    int w = t>>5, lane = t&31;
    const float* hrow = sH[w];
    float partial = 0.f;
    #pragma unroll
    for (int jj=0;jj<4;jj++){
        int j = lane + jj*32;
        float accv = sb2[j];
        #pragma unroll 8
        for (int k=0;k<NW;k++) accv += sWT[k*128+j]*hrow[k];
        partial += sw3[j]*mishf(accv);
    }
    #pragma unroll
    for (int off=16;off;off>>=1) partial += __shfl_xor_sync(0xFFFFFFFFu, partial, off);
    if (lane==0) out[b*NS + x0 + w] = partial + fc3_b[0];
}

// ---------------- host: Daubechies filters via spectral factorization ----------------
static double binom_d(int n, int k){
    double r = 1.0;
    for (int i=1;i<=k;i++) r = r*(double)(n-k+i)/(double)i;
    return r;
}

static void db_lo(int N, double* h20){
    for (int i=0;i<LF;i++) h20[i]=0.0;
    int L = 2*N;
    std::vector<std::complex<double>> ch(N+1);
    double p2 = std::pow(0.5, N);
    for (int i=0;i<=N;i++) ch[i] = binom_d(N,i)*p2;
    if (N > 1){
        // Q polynomial
        std::vector<double> Q(2*N-1, 0.0);
        const double base[3] = {-0.25, 0.5, -0.25};
        for (int k=0;k<N;k++){
            std::vector<double> tt(1, 1.0);
            for (int p=0;p<k;p++){
                std::vector<double> r2(tt.size()+2, 0.0);
                for (size_t a=0;a<tt.size();a++)
                    for (int bb=0;bb<3;bb++) r2[a+bb] += tt[a]*base[bb];
                tt.swap(r2);
            }
            double pyk = binom_d(N-1+k, k);
            for (size_t j=0;j<tt.size();j++) Q[N-1-k+j] += pyk*tt[j];
        }
        int deg = 2*N-2;
        std::vector<std::complex<double>> c(deg);
        for (int mth=0;mth<deg;mth++) c[mth] = Q[mth]/Q[deg];
        // Durand-Kerner
        std::vector<std::complex<double>> z(deg);
        std::complex<double> seed(0.4,0.9), curz(1.0,0.0);
        for (int i=0;i<deg;i++){ curz *= seed; z[i]=curz; }
        for (int it=0; it<2000; it++){
            for (int i=0;i<deg;i++){
                std::complex<double> pv(1.0,0.0);
                for (int mth=deg-1;mth>=0;mth--) pv = pv*z[i] + c[mth];
                std::complex<double> den(1.0,0.0);
                for (int j=0;j<deg;j++) if (j!=i) den *= (z[i]-z[j]);
                if (std::abs(den) < 1e-300) den = 1e-300;
                z[i] -= pv/den;
            }
        }
        for (int i=0;i<deg;i++){
            if (std::abs(z[i]) < 1.0){
                std::complex<double> r = z[i];
                std::complex<double> inv = 1.0/(std::complex<double>(1.0,0.0) - r);
                std::vector<std::complex<double>> nh(ch.size()+1, std::complex<double>(0.0,0.0));
                for (size_t a=0;a<ch.size();a++){
                    nh[a]   += ch[a]*(-r)*inv;
                    nh[a+1] += ch[a]*inv;
                }
                ch.swap(nh);
            }
        }
    }
    double s2 = std::sqrt(2.0);
    for (int i=0;i<L && i<(int)ch.size() && i<LF;i++) h20[i] = ch[i].real()*s2;
}

static Filters make_filters(){
    Filters F;
    for (int e=0;e<NE;e++){
        int N = e+1, L = 2*N;
        double h[LF];
        db_lo(N, h);
        for (int tp=0;tp<LF;tp++){
            F.f[e][0][tp] = (float)h[tp];
            // g[t] = h[L-1-t] * (-1)^t, zero-padded
            F.f[e][1][tp] = (tp < L) ? (float)(h[L-1-tp] * ((tp&1)?-1.0:1.0)) : 0.f;
        }
    }
    return F;
}

// ---------------- launch ----------------
extern "C" void kernel_launch(void* const* d_in, const int* in_sizes, int n_in,
                              void* d_out, int out_size){
    const float* x     = (const float*)d_in[0];
    const float* label = (const float*)d_in[1];
    const float* fc0_w = (const float*)d_in[2];
    const float* fc0_b = (const float*)d_in[3];
    const float* fc1_w = (const float*)d_in[4];
    const float* fc1_b = (const float*)d_in[5];
    const float* gwl   = (const float*)d_in[6];
    const float* gbl   = (const float*)d_in[7];
    const float* gwg   = (const float*)d_in[8];
    const float* gbg   = (const float*)d_in[9];
    const float* ew1   = (const float*)d_in[10];
    const float* ew2   = (const float*)d_in[11];
    const float* ww    = (const float*)d_in[12];
    const float* wb    = (const float*)d_in[13];
    const float* fc2_w = (const float*)d_in[14];
    const float* fc2_b = (const float*)d_in[15];
    const float* fc3_w = (const float*)d_in[16];
    const float* fc3_b = (const float*)d_in[17];

    Filters F = make_filters();

    float *dA=nullptr,*dB=nullptr,*dCorr=nullptr,*dS=nullptr,*dCoef=nullptr,*dDelta=nullptr;
    cudaGetSymbolAddress((void**)&dA,    g_bufA);
    cudaGetSymbolAddress((void**)&dB,    g_bufB);
    cudaGetSymbolAddress((void**)&dCorr, g_corr);
    cudaGetSymbolAddress((void**)&dS,    g_S);
    cudaGetSymbolAddress((void**)&dCoef, g_coef);
    cudaGetSymbolAddress((void**)&dDelta,g_delta);

    build_syn_kernel<<<NE*2*NM, 128>>>(F);
    prep_lift_kernel<<<1, 64>>>(fc0_w, fc0_b, fc1_w, fc1_b);
    lift_kernel<<<(NROW*NS)/256, 256>>>(x);
    xf_kernel<<<NROW, 256>>>(dA);
    gate_kernel<<<1, 256>>>(label, gwl, gbl, gwg, gbg);

    float* cur = dA; float* nxt = dB;
    for (int hd=0; hd<NHID; hd++){
        sgemm_kernel<0><<<dim3(NCOL/128, NROW/128), 256>>>(cur, dS, dCoef, NROW, NCOL, NS);
        mix_kernel<<<dim3(NM, NE), 256>>>(ew1, ew2, hd);
        sgemm_kernel<1><<<dim3(NS/128, NROW/128), 256>>>(dDelta, dS, dCorr, NROW, NS, NCOL);
        combine_kernel<<<dim3(NS/64, NB), 256>>>(cur, dCorr, ww, wb, nxt, hd);
        float* tp = cur; cur = nxt; nxt = tp;
    }
    head_kernel<<<dim3(NS/8, NB), 256>>>(cur, fc2_w, fc2_b, fc3_w, fc3_b, (float*)d_out);
}

// round 3
// speedup vs baseline: 2.0946x; 2.0946x over previous
#include <cuda_runtime.h>
#include <cuda_bf16.h>
#include <cmath>
#include <vector>
#include <complex>
#include <cstdint>

// ---------------- problem constants ----------------
#define NE   10
#define LF   20
#define NB   32
#define NW   64
#define NS   1024
#define NM   64
#define NHID 4
#define NROW (NB*NW)     // 2048
#define NCOL (NE*2*NM)   // 1280

// ---------------- device scratch ----------------
__device__ float g_bufA [NROW*NS];
__device__ float g_bufB [NROW*NS];
__device__ float g_corr [NROW*NS];
__device__ float g_coefT[NCOL*NROW];      // [col][row]
__device__ float g_deltaT[NCOL*NROW];     // [col][row]
__device__ __nv_bfloat16 g_Hhi[NROW*NS],  g_Hlo[NROW*NS];    // h split, row-major [row][x]
__device__ __nv_bfloat16 g_Dhi[NROW*NCOL],g_Dlo[NROW*NCOL];  // delta split, [row][col]
__device__ __nv_bfloat16 g_StHi[NCOL*NS], g_StLo[NCOL*NS];   // S^T  [col][x]
__device__ __nv_bfloat16 g_SxHi[NS*NCOL], g_SxLo[NS*NCOL];   // S    [x][col]
__device__ float g_Wt1[(size_t)NHID*NE*NM*NW*NW];            // [hd][e][m][i][o]
__device__ float g_Wt2[(size_t)NHID*NE*NM*NW*NW];
__device__ float g_xf [NROW];
__device__ float g_lam[NHID*NB*NE];
__device__ float g_A2 [NW*2];
__device__ float g_Bc [NW];

struct Filters { float f[NE][2][LF]; };

__device__ __forceinline__ float mishf(float x){
    float sp = (x > 20.f) ? x : log1pf(expf(x));
    return x * tanhf(sp);
}

__device__ __forceinline__ uint32_t s2u(const void* p){
    uint32_t a;
    asm("{ .reg .u64 t; cvta.to.shared.u64 t, %1; cvt.u32.u64 %0, t; }" : "=r"(a) : "l"(p));
    return a;
}

__device__ __forceinline__ void cpasync16(uint32_t d, const void* g){
    asm volatile("cp.async.cg.shared.global [%0], [%1], 16;" :: "r"(d), "l"(g));
}

#define LDMX4(r, a) \
    asm volatile("ldmatrix.sync.aligned.m8n8.x4.shared.b16 {%0,%1,%2,%3}, [%4];" \
        : "=r"((r)[0]),"=r"((r)[1]),"=r"((r)[2]),"=r"((r)[3]) : "r"(a))

#define MMA16816(c, a, b) \
    asm volatile("mma.sync.aligned.m16n8k16.row.col.f32.bf16.bf16.f32 " \
        "{%0,%1,%2,%3}, {%4,%5,%6,%7}, {%8,%9}, {%0,%1,%2,%3};" \
        : "+f"((c)[0]),"+f"((c)[1]),"+f"((c)[2]),"+f"((c)[3]) \
        : "r"((a)[0]),"r"((a)[1]),"r"((a)[2]),"r"((a)[3]), "r"((b)[0]),"r"((b)[1]))

// ---------------- build synthesis matrix (both layouts, split bf16) ----------------
__global__ __launch_bounds__(128) void build_syn_kernel(Filters F){
    __shared__ float b0[NS], b1[NS];
    int bid = blockIdx.x;
    int m = bid & 63, tt = (bid>>6)&1, e = bid>>7;
    int t = threadIdx.x;
    float* cur = b0; float* nxt = b1;
    for (int i=t;i<64;i+=128) cur[i] = (i==m)?1.f:0.f;
    __syncthreads();
    int n_in = 64;
    #pragma unroll
    for (int s=0;s<4;s++){
        int n_out = n_in<<1;
        const float* f = (s==0 && tt==1) ? F.f[e][1] : F.f[e][0];
        for (int x=t;x<n_out;x+=128){
            int j0 = x>>1, par = x&1;
            float acc = 0.f;
            #pragma unroll
            for (int u=0;u<10;u++){
                int j = j0-u; if (j<0) j += n_in;
                acc += cur[j]*f[par+2*u];
            }
            nxt[x]=acc;
        }
        __syncthreads();
        float* tp=cur; cur=nxt; nxt=tp;
        n_in = n_out;
    }
    int col = (e*2+tt)*64+m;
    for (int x=t;x<NS;x+=128){
        float v = cur[x];
        __nv_bfloat16 h = __float2bfloat16_rn(v);
        __nv_bfloat16 l = __float2bfloat16_rn(v - __bfloat162float(h));
        g_StHi[(size_t)col*NS + x] = h;
        g_StLo[(size_t)col*NS + x] = l;
        g_SxHi[(size_t)x*NCOL + col] = h;
        g_SxLo[(size_t)x*NCOL + col] = l;
    }
}

// ---------------- transpose expert weights -> [hd][e][m][i][o] ----------------
__global__ __launch_bounds__(256) void transw_kernel(const float* __restrict__ w1,
                                                     const float* __restrict__ w2){
    __shared__ float sT[64][65];
    int i  = blockIdx.x;
    int he = blockIdx.y;
    size_t inb  = ((size_t)he*NW + i)*NW*NM;
    size_t outb = (size_t)he*NM*NW*NW;
    int t = threadIdx.x;
    for (int s=0;s<2;s++){
        const float* W = s ? w2 : w1;
        float* O = s ? g_Wt2 : g_Wt1;
        __syncthreads();
        #pragma unroll
        for (int k=0;k<16;k++){ int idx=t+k*256; int o=idx>>6, m=idx&63; sT[o][m]=W[inb + (size_t)o*NM + m]; }
        __syncthreads();
        #pragma unroll
        for (int k=0;k<16;k++){ int idx=t+k*256; int m=idx>>6, o=idx&63; O[outb + ((size_t)m*NW + i)*NW + o] = sT[o][m]; }
    }
}

// ---------------- lift ----------------
__global__ void prep_lift_kernel(const float* __restrict__ fc0_w, const float* __restrict__ fc0_b,
                                 const float* __restrict__ fc1_w, const float* __restrict__ fc1_b){
    int c = threadIdx.x;
    if (c >= NW) return;
    float a0=0.f,a1=0.f,bb=0.f;
    for (int k=0;k<NW;k++){
        float w = fc1_w[c*NW+k];
        a0 += w*fc0_w[k*2+0];
        a1 += w*fc0_w[k*2+1];
        bb += w*fc0_b[k];
    }
    g_A2[c*2]=a0; g_A2[c*2+1]=a1; g_Bc[c]=bb+fc1_b[c];
}

__global__ __launch_bounds__(256) void lift_kernel(const float* __restrict__ x){
    int idx = blockIdx.x*256 + threadIdx.x;
    if (idx >= NROW*NS) return;
    int xp = idx & (NS-1);
    int c  = (idx>>10)&63;
    int b  = idx>>16;
    float xv = x[b*NS+xp];
    float gv = (float)xp*(1.f/1023.f);
    g_bufA[idx] = g_A2[c*2]*xv + g_A2[c*2+1]*gv + g_Bc[c];
}

// ---------------- xf ----------------
__global__ __launch_bounds__(256) void xf_kernel(const float* __restrict__ h){
    __shared__ float red[256];
    int r = blockIdx.x, t = threadIdx.x;
    float s = 0.f;
    for (int xp=t; xp<NS; xp+=256) s += h[r*NS+xp];
    red[t]=s; __syncthreads();
    for (int o=128;o;o>>=1){ if (t<o) red[t]+=red[t+o]; __syncthreads(); }
    if (t==0) g_xf[r] = red[0]*(1.f/1024.f);
}

// ---------------- gates ----------------
__global__ __launch_bounds__(256) void gate_kernel(const float* __restrict__ label,
        const float* __restrict__ wl, const float* __restrict__ bl,
        const float* __restrict__ wg, const float* __restrict__ bg){
    __shared__ float s_lf[NHID][32];
    __shared__ float s_logit[NHID][NB][NE];
    __shared__ float s_xf[NB][NW];
    __shared__ float s_labsum;
    int t = threadIdx.x;
    if (t==0){ float s=0.f; for(int l=0;l<10;l++) s+=label[l]; s_labsum=s; }
    for (int idx=t; idx<NB*NW; idx+=256) s_xf[idx>>6][idx&63] = g_xf[idx];
    __syncthreads();
    if (t < 128){
        int hd=t>>5, o=t&31;
        float s=0.f;
        for (int c=0;c<NW;c++) s += wl[(hd*32+o)*NW+c];
        s_lf[hd][o] = s*s_labsum*0.1f + bl[hd*32+o];
    }
    __syncthreads();
    for (int idx=t; idx<NHID*NB*NE; idx+=256){
        int hd = idx/(NB*NE); int r = idx%(NB*NE); int b=r/NE, e=r%NE;
        const float* w = &wg[(hd*NE+e)*96];
        float s = bg[hd*NE+e];
        for (int c=0;c<NW;c++) s += s_xf[b][c]*w[c];
        for (int o=0;o<32;o++)  s += s_lf[hd][o]*w[64+o];
        s_logit[hd][b][e]=s;
    }
    __syncthreads();
    if (t < 128){
        int hd=t>>5, b=t&31;
        float mx=-1e30f;
        for (int e=0;e<NE;e++) mx = fmaxf(mx, s_logit[hd][b][e]);
        float ex[NE]; float sum=0.f;
        for (int e=0;e<NE;e++){ ex[e]=expf(s_logit[hd][b][e]-mx); sum+=ex[e]; }
        float inv = 1.f/sum;
        for (int e=0;e<NE;e++) g_lam[(hd*NB+b)*NE+e] = ex[e]*inv;
    }
}

// ---------------- split fp32 -> bf16 hi/lo ----------------
__global__ __launch_bounds__(256) void split_kernel(const float* __restrict__ src,
        __nv_bfloat16* __restrict__ hi, __nv_bfloat16* __restrict__ lo, int n4){
    int i = blockIdx.x*256 + threadIdx.x;
    if (i >= n4) return;
    float4 v = ((const float4*)src)[i];
    __nv_bfloat16 h0=__float2bfloat16_rn(v.x), h1=__float2bfloat16_rn(v.y);
    __nv_bfloat16 h2=__float2bfloat16_rn(v.z), h3=__float2bfloat16_rn(v.w);
    __nv_bfloat16 l0=__float2bfloat16_rn(v.x-__bfloat162float(h0));
    __nv_bfloat16 l1=__float2bfloat16_rn(v.y-__bfloat162float(h1));
    __nv_bfloat16 l2=__float2bfloat16_rn(v.z-__bfloat162float(h2));
    __nv_bfloat16 l3=__float2bfloat16_rn(v.w-__bfloat162float(h3));
    ((__nv_bfloat162*)hi)[i*2+0] = __halves2bfloat162(h0,h1);
    ((__nv_bfloat162*)hi)[i*2+1] = __halves2bfloat162(h2,h3);
    ((__nv_bfloat162*)lo)[i*2+0] = __halves2bfloat162(l0,l1);
    ((__nv_bfloat162*)lo)[i*2+1] = __halves2bfloat162(l2,l3);
}

// ---------------- transpose deltaT [col][row] -> Dhi/Dlo [row][col] bf16 ----------------
__global__ __launch_bounds__(256) void tsplit_kernel(){
    __shared__ float sT[32][33];
    int c0 = blockIdx.x*32, r0 = blockIdx.y*32;
    int t = threadIdx.x;
    #pragma unroll
    for (int i=0;i<4;i++){
        int idx=t+i*256; int cc=idx>>5, rr=idx&31;
        sT[cc][rr] = g_deltaT[(size_t)(c0+cc)*NROW + r0+rr];
    }
    __syncthreads();
    #pragma unroll
    for (int i=0;i<2;i++){
        int idx=t+i*256; int rr=idx>>4, c2=(idx&15)*2;
        float v0=sT[c2][rr], v1=sT[c2+1][rr];
        __nv_bfloat16 h0=__float2bfloat16_rn(v0), h1=__float2bfloat16_rn(v1);
        __nv_bfloat16 l0=__float2bfloat16_rn(v0-__bfloat162float(h0));
        __nv_bfloat16 l1=__float2bfloat16_rn(v1-__bfloat162float(h1));
        size_t o = (size_t)(r0+rr)*NCOL + c0+c2;
        *(__nv_bfloat162*)&g_Dhi[o] = __halves2bfloat162(h0,h1);
        *(__nv_bfloat162*)&g_Dlo[o] = __halves2bfloat162(l0,l1);
    }
}

// ---------------- mma.sync split-bf16 GEMM ----------------
// C[M][N] = sum_k A[m][k]*B[n][k] with A=Ah+Al, B=Bh+Bl (3-term).
// TRANS_OUT=1: write C^T (C[n][m], ld=M). Else C[m][n], ld=N.
#define LDS_PAD 40
#define TILE_E  (128*LDS_PAD)          // elements per tile
#define BUF_E   (4*TILE_E)             // elements per buffer
#define GEMM_SMEM (2*BUF_E*2)          // bytes (81920)

template<int TRANS_OUT>
__global__ __launch_bounds__(256,1) void gemm_kernel(
        const __nv_bfloat16* __restrict__ Ah, const __nv_bfloat16* __restrict__ Al,
        const __nv_bfloat16* __restrict__ Bh, const __nv_bfloat16* __restrict__ Bl,
        float* __restrict__ C, int M, int N, int K){
    extern __shared__ char smem[];
    uint32_t sbase = s2u(smem);
    int t = threadIdx.x, lane = t&31, wid = t>>5;
    int wm = wid>>2, wn = wid&3;
    int row0 = blockIdx.y*128, col0 = blockIdx.x*128;

    float acc[4][4][4];
    #pragma unroll
    for (int i=0;i<4;i++)
        #pragma unroll
        for (int j=0;j<4;j++)
            #pragma unroll
            for (int r=0;r<4;r++) acc[i][j][r]=0.f;

    // ldmatrix lane address components
    int arow = lane & 15;           int akk = (lane>>4)<<3;
    int bn   = (lane&7) + ((lane>>4)<<3);
    int bk   = lane & 8;

    int NC = K >> 5;

    auto issue = [&](int c, int buf){
        int k0 = c<<5;
        uint32_t sb = sbase + (uint32_t)buf*BUF_E*2;
        #pragma unroll
        for (int i=0;i<2;i++){
            int idx = t + i*256;
            int r = idx>>2, cg = idx&3;
            uint32_t doff = (uint32_t)(r*LDS_PAD + cg*8)*2;
            size_t ga = (size_t)(row0+r)*K + k0 + cg*8;
            size_t gb = (size_t)(col0+r)*K + k0 + cg*8;
            cpasync16(sb + 0*TILE_E*2 + doff, Ah + ga);
            cpasync16(sb + 1*TILE_E*2 + doff, Al + ga);
            cpasync16(sb + 2*TILE_E*2 + doff, Bh + gb);
            cpasync16(sb + 3*TILE_E*2 + doff, Bl + gb);
        }
        asm volatile("cp.async.commit_group;");
    };

    issue(0, 0);
    for (int c=0; c<NC; c++){
        if (c+1 < NC){
            issue(c+1, (c+1)&1);
            asm volatile("cp.async.wait_group 1;");
        } else {
            asm volatile("cp.async.wait_group 0;");
        }
        __syncthreads();

        uint32_t sb = sbase + (uint32_t)(c&1)*BUF_E*2;
        uint32_t aH = sb, aL = sb+TILE_E*2, bH = sb+2*TILE_E*2, bL = sb+3*TILE_E*2;
        #pragma unroll
        for (int ks=0; ks<2; ks++){
            uint32_t ah[4][4], al[4][4], bh[4][2], bl[4][2];
            #pragma unroll
            for (int i=0;i<4;i++){
                uint32_t ra = (uint32_t)((wm*64 + i*16 + arow)*LDS_PAD + ks*16 + akk)*2;
                LDMX4(ah[i], aH+ra);
                LDMX4(al[i], aL+ra);
            }
            #pragma unroll
            for (int j2=0;j2<2;j2++){
                uint32_t rb = (uint32_t)((wn*32 + j2*16 + bn)*LDS_PAD + ks*16 + bk)*2;
                uint32_t r1[4], r2[4];
                LDMX4(r1, bH+rb);
                bh[2*j2][0]=r1[0]; bh[2*j2][1]=r1[1]; bh[2*j2+1][0]=r1[2]; bh[2*j2+1][1]=r1[3];
                LDMX4(r2, bL+rb);
                bl[2*j2][0]=r2[0]; bl[2*j2][1]=r2[1]; bl[2*j2+1][0]=r2[2]; bl[2*j2+1][1]=r2[3];
            }
            #pragma unroll
            for (int i=0;i<4;i++)
                #pragma unroll
                for (int j=0;j<4;j++){
                    MMA16816(acc[i][j], ah[i], bh[j]);
                    MMA16816(acc[i][j], ah[i], bl[j]);
                    MMA16816(acc[i][j], al[i], bh[j]);
                }
        }
        __syncthreads();
    }

    if (TRANS_OUT){
        // stage per-warp 64x32 into smem as [col][row], then coalesced column writes
        float* ep = (float*)smem + (size_t)wid*(32*65);
        #pragma unroll
        for (int i=0;i<4;i++)
            #pragma unroll
            for (int j=0;j<4;j++){
                int rl = i*16 + (lane>>2);
                int cl = j*8 + 2*(lane&3);
                ep[cl*65 + rl]        = acc[i][j][0];
                ep[(cl+1)*65 + rl]    = acc[i][j][1];
                ep[cl*65 + rl + 8]    = acc[i][j][2];
                ep[(cl+1)*65 + rl + 8]= acc[i][j][3];
            }
        __syncwarp();
        #pragma unroll 4
        for (int cc=0; cc<32; cc++){
            int colg = col0 + wn*32 + cc;
            float* dst = C + (size_t)colg*M + row0 + wm*64;
            dst[lane]      = ep[cc*65 + lane];
            dst[lane + 32] = ep[cc*65 + lane + 32];
        }
    } else {
        #pragma unroll
        for (int i=0;i<4;i++)
            #pragma unroll
            for (int j=0;j<4;j++){
                int rg = row0 + wm*64 + i*16 + (lane>>2);
                int cg = col0 + wn*32 + j*8 + 2*(lane&3);
                C[(size_t)rg*N + cg]       = acc[i][j][0];
                C[(size_t)rg*N + cg + 1]   = acc[i][j][1];
                C[(size_t)(rg+8)*N + cg]   = acc[i][j][2];
                C[(size_t)(rg+8)*N + cg+1] = acc[i][j][3];
            }
    }
}

// ---------------- mix: deltaT = lam*(W^T a - a) ----------------
__global__ __launch_bounds__(256) void mix_kernel(int hd){
    __shared__ float sC[NROW];
    __shared__ float sW[NW*NW];
    int m = blockIdx.x, e = blockIdx.y, t = threadIdx.x;
    size_t wb = ((size_t)(hd*NE+e)*NM + m)*NW*NW;
    #pragma unroll
    for (int tt=0; tt<2; tt++){
        const float* Wp = tt ? g_Wt2 : g_Wt1;
        int col = (e*2+tt)*NM + m;
        __syncthreads();
        for (int i=t;i<NROW;i+=256) sC[i] = g_coefT[(size_t)col*NROW + i];
        for (int i=t;i<NW*NW;i+=256) sW[i] = Wp[wb + i];
        __syncthreads();
        for (int oi=t; oi<NROW; oi+=256){
            int b = oi>>6, o = oi&63;
            float acc = -sC[oi];
            const float* cbp = &sC[b*NW];
            #pragma unroll 8
            for (int i=0;i<NW;i++) acc += cbp[i]*sW[i*NW+o];
            g_deltaT[(size_t)col*NROW + oi] = acc * g_lam[(hd*NB+b)*NE+e];
        }
    }
}

// ---------------- combine ----------------
__global__ __launch_bounds__(256) void combine_kernel(const float* __restrict__ hin,
        const float* __restrict__ corr, const float* __restrict__ ww,
        const float* __restrict__ wb, float* __restrict__ hout, int hd){
    __shared__ float sH[NW][65];
    __shared__ float sW[NW][NW];
    int b = blockIdx.y, x0 = blockIdx.x*64, t = threadIdx.x;
    for (int idx=t; idx<NW*64; idx+=256){
        int c=idx>>6, xx=idx&63;
        sH[c][xx] = hin[(b*NW+c)*NS + x0+xx];
    }
    for (int idx=t; idx<NW*NW; idx+=256) sW[idx>>6][idx&63] = ww[hd*NW*NW+idx];
    __syncthreads();
    for (int idx=t; idx<NW*64; idx+=256){
        int c=idx>>6, xx=idx&63;
        float accv = wb[hd*NW+c];
        #pragma unroll 8
        for (int k=0;k<NW;k++) accv += sW[c][k]*sH[k][xx];
        int gi = (b*NW+c)*NS + x0+xx;
        float pre = sH[c][xx] + corr[gi] + accv;
        hout[gi] = mishf(pre);
    }
}

// ---------------- head ----------------
__global__ __launch_bounds__(256) void head_kernel(const float* __restrict__ hin,
        const float* __restrict__ fc2_w, const float* __restrict__ fc2_b,
        const float* __restrict__ fc3_w, const float* __restrict__ fc3_b,
        float* __restrict__ out){
    __shared__ float sWT[NW*128];
    __shared__ float sH[8][NW];
    __shared__ float sb2[128], sw3[128];
    int b = blockIdx.y, x0 = blockIdx.x*8, t = threadIdx.x;
    for (int idx=t; idx<128*NW; idx+=256){
        int j=idx>>6, k=idx&63;
        sWT[k*128+j] = fc2_w[idx];
    }
    if (t<128){ sb2[t]=fc2_b[t]; sw3[t]=fc3_w[t]; }
    for (int idx=t; idx<8*NW; idx+=256){
        int c = idx>>3, xx = idx&7;
        sH[xx][c] = hin[(b*NW+c)*NS + x0+xx];
    }
    __syncthreads();
    int w = t>>5, lane = t&31;
    const float* hrow = sH[w];
    float partial = 0.f;
    #pragma unroll
    for (int jj=0;jj<4;jj++){
        int j = lane + jj*32;
        float accv = sb2[j];
        #pragma unroll 8
        for (int k=0;k<NW;k++) accv += sWT[k*128+j]*hrow[k];
        partial += sw3[j]*mishf(accv);
    }
    #pragma unroll
    for (int off=16;off;off>>=1) partial += __shfl_xor_sync(0xFFFFFFFFu, partial, off);
    if (lane==0) out[b*NS + x0 + w] = partial + fc3_b[0];
}

// ---------------- host: Daubechies filters ----------------
static double binom_d(int n, int k){
    double r = 1.0;
    for (int i=1;i<=k;i++) r = r*(double)(n-k+i)/(double)i;
    return r;
}
static void db_lo(int N, double* h20){
    for (int i=0;i<LF;i++) h20[i]=0.0;
    int L = 2*N;
    std::vector<std::complex<double>> ch(N+1);
    double p2 = std::pow(0.5, N);
    for (int i=0;i<=N;i++) ch[i] = binom_d(N,i)*p2;
    if (N > 1){
        std::vector<double> Q(2*N-1, 0.0);
        const double base[3] = {-0.25, 0.5, -0.25};
        for (int k=0;k<N;k++){
            std::vector<double> tt(1, 1.0);
            for (int p=0;p<k;p++){
                std::vector<double> r2(tt.size()+2, 0.0);
                for (size_t a=0;a<tt.size();a++)
                    for (int bb=0;bb<3;bb++) r2[a+bb] += tt[a]*base[bb];
                tt.swap(r2);
            }
            double pyk = binom_d(N-1+k, k);
            for (size_t j=0;j<tt.size();j++) Q[N-1-k+j] += pyk*tt[j];
        }
        int deg = 2*N-2;
        std::vector<std::complex<double>> c(deg);
        for (int mth=0;mth<deg;mth++) c[mth] = Q[mth]/Q[deg];
        std::vector<std::complex<double>> z(deg);
        std::complex<double> seed(0.4,0.9), curz(1.0,0.0);
        for (int i=0;i<deg;i++){ curz *= seed; z[i]=curz; }
        for (int it=0; it<2000; it++){
            for (int i=0;i<deg;i++){
                std::complex<double> pv(1.0,0.0);
                for (int mth=deg-1;mth>=0;mth--) pv = pv*z[i] + c[mth];
                std::complex<double> den(1.0,0.0);
                for (int j=0;j<deg;j++) if (j!=i) den *= (z[i]-z[j]);
                if (std::abs(den) < 1e-300) den = 1e-300;
                z[i] -= pv/den;
            }
        }
        for (int i=0;i<deg;i++){
            if (std::abs(z[i]) < 1.0){
                std::complex<double> r = z[i];
                std::complex<double> inv = 1.0/(std::complex<double>(1.0,0.0) - r);
                std::vector<std::complex<double>> nh(ch.size()+1, std::complex<double>(0.0,0.0));
                for (size_t a=0;a<ch.size();a++){
                    nh[a]   += ch[a]*(-r)*inv;
                    nh[a+1] += ch[a]*inv;
                }
                ch.swap(nh);
            }
        }
    }
    double s2 = std::sqrt(2.0);
    for (int i=0;i<L && i<(int)ch.size() && i<LF;i++) h20[i] = ch[i].real()*s2;
}
static Filters make_filters(){
    Filters F;
    for (int e=0;e<NE;e++){
        int N = e+1, L = 2*N;
        double h[LF];
        db_lo(N, h);
        for (int tp=0;tp<LF;tp++){
            F.f[e][0][tp] = (float)h[tp];
            F.f[e][1][tp] = (tp < L) ? (float)(h[L-1-tp] * ((tp&1)?-1.0:1.0)) : 0.f;
        }
    }
    return F;
}

// ---------------- launch ----------------
extern "C" void kernel_launch(void* const* d_in, const int* in_sizes, int n_in,
                              void* d_out, int out_size){
    const float* x     = (const float*)d_in[0];
    const float* label = (const float*)d_in[1];
    const float* fc0_w = (const float*)d_in[2];
    const float* fc0_b = (const float*)d_in[3];
    const float* fc1_w = (const float*)d_in[4];
    const float* fc1_b = (const float*)d_in[5];
    const float* gwl   = (const float*)d_in[6];
    const float* gbl   = (const float*)d_in[7];
    const float* gwg   = (const float*)d_in[8];
    const float* gbg   = (const float*)d_in[9];
    const float* ew1   = (const float*)d_in[10];
    const float* ew2   = (const float*)d_in[11];
    const float* ww    = (const float*)d_in[12];
    const float* wb    = (const float*)d_in[13];
    const float* fc2_w = (const float*)d_in[14];
    const float* fc2_b = (const float*)d_in[15];
    const float* fc3_w = (const float*)d_in[16];
    const float* fc3_b = (const float*)d_in[17];

    Filters F = make_filters();

    float *dA, *dB, *dCorr, *dCoefT;
    __nv_bfloat16 *dHhi,*dHlo,*dDhi,*dDlo,*dStHi,*dStLo,*dSxHi,*dSxLo;
    cudaGetSymbolAddress((void**)&dA,    g_bufA);
    cudaGetSymbolAddress((void**)&dB,    g_bufB);
    cudaGetSymbolAddress((void**)&dCorr, g_corr);
    cudaGetSymbolAddress((void**)&dCoefT,g_coefT);
    cudaGetSymbolAddress((void**)&dHhi,  g_Hhi);
    cudaGetSymbolAddress((void**)&dHlo,  g_Hlo);
    cudaGetSymbolAddress((void**)&dDhi,  g_Dhi);
    cudaGetSymbolAddress((void**)&dDlo,  g_Dlo);
    cudaGetSymbolAddress((void**)&dStHi, g_StHi);
    cudaGetSymbolAddress((void**)&dStLo, g_StLo);
    cudaGetSymbolAddress((void**)&dSxHi, g_SxHi);
    cudaGetSymbolAddress((void**)&dSxLo, g_SxLo);

    cudaFuncSetAttribute(gemm_kernel<0>, cudaFuncAttributeMaxDynamicSharedMemorySize, GEMM_SMEM);
    cudaFuncSetAttribute(gemm_kernel<1>, cudaFuncAttributeMaxDynamicSharedMemorySize, GEMM_SMEM);

    build_syn_kernel<<<NE*2*NM, 128>>>(F);
    transw_kernel<<<dim3(64, NHID*NE), 256>>>(ew1, ew2);
    prep_lift_kernel<<<1, 64>>>(fc0_w, fc0_b, fc1_w, fc1_b);
    lift_kernel<<<(NROW*NS)/256, 256>>>(x);
    xf_kernel<<<NROW, 256>>>(dA);
    gate_kernel<<<1, 256>>>(label, gwl, gbl, gwg, gbg);

    float* cur = dA; float* nxt = dB;
    for (int hd=0; hd<NHID; hd++){
        split_kernel<<<(NROW*NS/4)/256, 256>>>(cur, dHhi, dHlo, NROW*NS/4);
        gemm_kernel<1><<<dim3(NCOL/128, NROW/128), 256, GEMM_SMEM>>>(
            dHhi, dHlo, dStHi, dStLo, dCoefT, NROW, NCOL, NS);
        mix_kernel<<<dim3(NM, NE), 256>>>(hd);
        tsplit_kernel<<<dim3(NCOL/32, NROW/32), 256>>>();
        gemm_kernel<0><<<dim3(NS/128, NROW/128), 256, GEMM_SMEM>>>(
            dDhi, dDlo, dSxHi, dSxLo, dCorr, NROW, NS, NCOL);
        combine_kernel<<<dim3(NS/64, NB), 256>>>(cur, dCorr, ww, wb, nxt, hd);
        float* tp = cur; cur = nxt; nxt = tp;
    }
    head_kernel<<<dim3(NS/8, NB), 256>>>(cur, fc2_w, fc2_b, fc3_w, fc3_b, (float*)d_out);
}

// round 4
// speedup vs baseline: 2.1800x; 1.0408x over previous
#include <cuda_runtime.h>
#include <cuda_bf16.h>
#include <cmath>
#include <vector>
#include <complex>
#include <cstdint>

// ---------------- problem constants ----------------
#define NE   10
#define LF   20
#define NB   32
#define NW   64
#define NS   1024
#define NM   64
#define NHID 4
#define NROW (NB*NW)     // 2048
#define NCOL (NE*2*NM)   // 1280

// ---------------- device scratch ----------------
__device__ float g_bufA [NROW*NS];
__device__ float g_bufB [NROW*NS];
__device__ float g_corr [NROW*NS];
__device__ float g_coefT[NCOL*NROW];      // [col][row]
__device__ float g_deltaT[NCOL*NROW];     // [col][row]
__device__ __nv_bfloat16 g_Hhi[NROW*NS],  g_Hlo[NROW*NS];    // h split, row-major [row][x]
__device__ __nv_bfloat16 g_Dhi[NROW*NCOL],g_Dlo[NROW*NCOL];  // delta split, [row][col]
__device__ __nv_bfloat16 g_StHi[NCOL*NS], g_StLo[NCOL*NS];   // S^T  [col][x]
__device__ __nv_bfloat16 g_SxHi[NS*NCOL], g_SxLo[NS*NCOL];   // S    [x][col]
__device__ float g_Wt1[(size_t)NHID*NE*NM*NW*NW];            // [hd][e][m][i][o]
__device__ float g_Wt2[(size_t)NHID*NE*NM*NW*NW];
__device__ float g_xf [NROW];
__device__ float g_lam[NHID*NB*NE];
__device__ float g_A2 [NW*2];
__device__ float g_Bc [NW];

struct Filters { float f[NE][2][LF]; };

__device__ __forceinline__ float mishf(float x){
    float sp = (x > 20.f) ? x : log1pf(expf(x));
    return x * tanhf(sp);
}

__device__ __forceinline__ uint32_t s2u(const void* p){
    uint32_t a;
    asm("{ .reg .u64 t; cvta.to.shared.u64 t, %1; cvt.u32.u64 %0, t; }" : "=r"(a) : "l"(p));
    return a;
}

__device__ __forceinline__ void cpasync16(uint32_t d, const void* g){
    asm volatile("cp.async.cg.shared.global [%0], [%1], 16;" :: "r"(d), "l"(g));
}

#define LDMX4(r, a) \
    asm volatile("ldmatrix.sync.aligned.m8n8.x4.shared.b16 {%0,%1,%2,%3}, [%4];" \
        : "=r"((r)[0]),"=r"((r)[1]),"=r"((r)[2]),"=r"((r)[3]) : "r"(a))

#define MMA16816(c, a, b) \
    asm volatile("mma.sync.aligned.m16n8k16.row.col.f32.bf16.bf16.f32 " \
        "{%0,%1,%2,%3}, {%4,%5,%6,%7}, {%8,%9}, {%0,%1,%2,%3};" \
        : "+f"((c)[0]),"+f"((c)[1]),"+f"((c)[2]),"+f"((c)[3]) \
        : "r"((a)[0]),"r"((a)[1]),"r"((a)[2]),"r"((a)[3]), "r"((b)[0]),"r"((b)[1]))

// ---------------- build synthesis matrix (both layouts, split bf16) ----------------
__global__ __launch_bounds__(128) void build_syn_kernel(Filters F){
    __shared__ float b0[NS], b1[NS];
    int bid = blockIdx.x;
    int m = bid & 63, tt = (bid>>6)&1, e = bid>>7;
    int t = threadIdx.x;
    float* cur = b0; float* nxt = b1;
    for (int i=t;i<64;i+=128) cur[i] = (i==m)?1.f:0.f;
    __syncthreads();
    int n_in = 64;
    #pragma unroll
    for (int s=0;s<4;s++){
        int n_out = n_in<<1;
        const float* f = (s==0 && tt==1) ? F.f[e][1] : F.f[e][0];
        for (int x=t;x<n_out;x+=128){
            int j0 = x>>1, par = x&1;
            float acc = 0.f;
            #pragma unroll
            for (int u=0;u<10;u++){
                int j = j0-u; if (j<0) j += n_in;
                acc += cur[j]*f[par+2*u];
            }
            nxt[x]=acc;
        }
        __syncthreads();
        float* tp=cur; cur=nxt; nxt=tp;
        n_in = n_out;
    }
    int col = (e*2+tt)*64+m;
    for (int x=t;x<NS;x+=128){
        float v = cur[x];
        __nv_bfloat16 h = __float2bfloat16_rn(v);
        __nv_bfloat16 l = __float2bfloat16_rn(v - __bfloat162float(h));
        g_StHi[(size_t)col*NS + x] = h;
        g_StLo[(size_t)col*NS + x] = l;
        g_SxHi[(size_t)x*NCOL + col] = h;
        g_SxLo[(size_t)x*NCOL + col] = l;
    }
}

// ---------------- transpose expert weights -> [hd][e][m][i][o] ----------------
__global__ __launch_bounds__(256) void transw_kernel(const float* __restrict__ w1,
                                                     const float* __restrict__ w2){
    __shared__ float sT[64][65];
    int i  = blockIdx.x;
    int he = blockIdx.y;
    size_t inb  = ((size_t)he*NW + i)*NW*NM;
    size_t outb = (size_t)he*NM*NW*NW;
    int t = threadIdx.x;
    for (int s=0;s<2;s++){
        const float* W = s ? w2 : w1;
        float* O = s ? g_Wt2 : g_Wt1;
        __syncthreads();
        #pragma unroll
        for (int k=0;k<16;k++){ int idx=t+k*256; int o=idx>>6, m=idx&63; sT[o][m]=W[inb + (size_t)o*NM + m]; }
        __syncthreads();
        #pragma unroll
        for (int k=0;k<16;k++){ int idx=t+k*256; int m=idx>>6, o=idx&63; O[outb + ((size_t)m*NW + i)*NW + o] = sT[o][m]; }
    }
}

// ---------------- lift ----------------
__global__ void prep_lift_kernel(const float* __restrict__ fc0_w, const float* __restrict__ fc0_b,
                                 const float* __restrict__ fc1_w, const float* __restrict__ fc1_b){
    int c = threadIdx.x;
    if (c >= NW) return;
    float a0=0.f,a1=0.f,bb=0.f;
    for (int k=0;k<NW;k++){
        float w = fc1_w[c*NW+k];
        a0 += w*fc0_w[k*2+0];
        a1 += w*fc0_w[k*2+1];
        bb += w*fc0_b[k];
    }
    g_A2[c*2]=a0; g_A2[c*2+1]=a1; g_Bc[c]=bb+fc1_b[c];
}

__global__ __launch_bounds__(256) void lift_kernel(const float* __restrict__ x){
    int idx = blockIdx.x*256 + threadIdx.x;
    if (idx >= NROW*NS) return;
    int xp = idx & (NS-1);
    int c  = (idx>>10)&63;
    int b  = idx>>16;
    float xv = x[b*NS+xp];
    float gv = (float)xp*(1.f/1023.f);
    g_bufA[idx] = g_A2[c*2]*xv + g_A2[c*2+1]*gv + g_Bc[c];
}

// ---------------- xf ----------------
__global__ __launch_bounds__(256) void xf_kernel(const float* __restrict__ h){
    __shared__ float red[256];
    int r = blockIdx.x, t = threadIdx.x;
    float s = 0.f;
    for (int xp=t; xp<NS; xp+=256) s += h[r*NS+xp];
    red[t]=s; __syncthreads();
    for (int o=128;o;o>>=1){ if (t<o) red[t]+=red[t+o]; __syncthreads(); }
    if (t==0) g_xf[r] = red[0]*(1.f/1024.f);
}

// ---------------- gates ----------------
__global__ __launch_bounds__(256) void gate_kernel(const float* __restrict__ label,
        const float* __restrict__ wl, const float* __restrict__ bl,
        const float* __restrict__ wg, const float* __restrict__ bg){
    __shared__ float s_lf[NHID][32];
    __shared__ float s_logit[NHID][NB][NE];
    __shared__ float s_xf[NB][NW];
    __shared__ float s_labsum;
    int t = threadIdx.x;
    if (t==0){ float s=0.f; for(int l=0;l<10;l++) s+=label[l]; s_labsum=s; }
    for (int idx=t; idx<NB*NW; idx+=256) s_xf[idx>>6][idx&63] = g_xf[idx];
    __syncthreads();
    if (t < 128){
        int hd=t>>5, o=t&31;
        float s=0.f;
        for (int c=0;c<NW;c++) s += wl[(hd*32+o)*NW+c];
        s_lf[hd][o] = s*s_labsum*0.1f + bl[hd*32+o];
    }
    __syncthreads();
    for (int idx=t; idx<NHID*NB*NE; idx+=256){
        int hd = idx/(NB*NE); int r = idx%(NB*NE); int b=r/NE, e=r%NE;
        const float* w = &wg[(hd*NE+e)*96];
        float s = bg[hd*NE+e];
        for (int c=0;c<NW;c++) s += s_xf[b][c]*w[c];
        for (int o=0;o<32;o++)  s += s_lf[hd][o]*w[64+o];
        s_logit[hd][b][e]=s;
    }
    __syncthreads();
    if (t < 128){
        int hd=t>>5, b=t&31;
        float mx=-1e30f;
        for (int e=0;e<NE;e++) mx = fmaxf(mx, s_logit[hd][b][e]);
        float ex[NE]; float sum=0.f;
        for (int e=0;e<NE;e++){ ex[e]=expf(s_logit[hd][b][e]-mx); sum+=ex[e]; }
        float inv = 1.f/sum;
        for (int e=0;e<NE;e++) g_lam[(hd*NB+b)*NE+e] = ex[e]*inv;
    }
}

// ---------------- split fp32 -> bf16 hi/lo ----------------
__global__ __launch_bounds__(256) void split_kernel(const float* __restrict__ src,
        __nv_bfloat16* __restrict__ hi, __nv_bfloat16* __restrict__ lo, int n4){
    int i = blockIdx.x*256 + threadIdx.x;
    if (i >= n4) return;
    float4 v = ((const float4*)src)[i];
    __nv_bfloat16 h0=__float2bfloat16_rn(v.x), h1=__float2bfloat16_rn(v.y);
    __nv_bfloat16 h2=__float2bfloat16_rn(v.z), h3=__float2bfloat16_rn(v.w);
    __nv_bfloat16 l0=__float2bfloat16_rn(v.x-__bfloat162float(h0));
    __nv_bfloat16 l1=__float2bfloat16_rn(v.y-__bfloat162float(h1));
    __nv_bfloat16 l2=__float2bfloat16_rn(v.z-__bfloat162float(h2));
    __nv_bfloat16 l3=__float2bfloat16_rn(v.w-__bfloat162float(h3));
    ((__nv_bfloat162*)hi)[i*2+0] = __halves2bfloat162(h0,h1);
    ((__nv_bfloat162*)hi)[i*2+1] = __halves2bfloat162(h2,h3);
    ((__nv_bfloat162*)lo)[i*2+0] = __halves2bfloat162(l0,l1);
    ((__nv_bfloat162*)lo)[i*2+1] = __halves2bfloat162(l2,l3);
}

// ---------------- transpose deltaT [col][row] -> Dhi/Dlo [row][col] bf16 ----------------
__global__ __launch_bounds__(256) void tsplit_kernel(){
    __shared__ float sT[32][33];
    int c0 = blockIdx.x*32, r0 = blockIdx.y*32;
    int t = threadIdx.x;
    #pragma unroll
    for (int i=0;i<4;i++){
        int idx=t+i*256; int cc=idx>>5, rr=idx&31;
        sT[cc][rr] = g_deltaT[(size_t)(c0+cc)*NROW + r0+rr];
    }
    __syncthreads();
    #pragma unroll
    for (int i=0;i<2;i++){
        int idx=t+i*256; int rr=idx>>4, c2=(idx&15)*2;
        float v0=sT[c2][rr], v1=sT[c2+1][rr];
        __nv_bfloat16 h0=__float2bfloat16_rn(v0), h1=__float2bfloat16_rn(v1);
        __nv_bfloat16 l0=__float2bfloat16_rn(v0-__bfloat162float(h0));
        __nv_bfloat16 l1=__float2bfloat16_rn(v1-__bfloat162float(h1));
        size_t o = (size_t)(r0+rr)*NCOL + c0+c2;
        *(__nv_bfloat162*)&g_Dhi[o] = __halves2bfloat162(h0,h1);
        *(__nv_bfloat162*)&g_Dlo[o] = __halves2bfloat162(l0,l1);
    }
}

// ---------------- mma.sync split-bf16 GEMM ----------------
// C[M][N] = sum_k A[m][k]*B[n][k] with A=Ah+Al, B=Bh+Bl (3-term).
// TRANS_OUT=1: write C^T (C[n][m], ld=M). Else C[m][n], ld=N.
#define LDS_PAD 40
#define TILE_E  (128*LDS_PAD)          // elements per tile
#define BUF_E   (4*TILE_E)             // elements per buffer
#define GEMM_SMEM (2*BUF_E*2)          // bytes (81920)

template<int TRANS_OUT>
__global__ __launch_bounds__(256,2) void gemm_kernel(
        const __nv_bfloat16* __restrict__ Ah, const __nv_bfloat16* __restrict__ Al,
        const __nv_bfloat16* __restrict__ Bh, const __nv_bfloat16* __restrict__ Bl,
        float* __restrict__ C, int M, int N, int K){
    extern __shared__ char smem[];
    uint32_t sbase = s2u(smem);
    int t = threadIdx.x, lane = t&31, wid = t>>5;
    int wm = wid>>2, wn = wid&3;
    int row0 = blockIdx.y*128, col0 = blockIdx.x*128;

    float acc[4][4][4];
    #pragma unroll
    for (int i=0;i<4;i++)
        #pragma unroll
        for (int j=0;j<4;j++)
            #pragma unroll
            for (int r=0;r<4;r++) acc[i][j][r]=0.f;

    // ldmatrix lane address components
    int arow = lane & 15;           int akk = (lane>>4)<<3;
    int bn   = (lane&7) + ((lane>>4)<<3);
    int bk   = lane & 8;

    int NC = K >> 5;

    auto issue = [&](int c, int buf){
        int k0 = c<<5;
        uint32_t sb = sbase + (uint32_t)buf*BUF_E*2;
        #pragma unroll
        for (int i=0;i<2;i++){
            int idx = t + i*256;
            int r = idx>>2, cg = idx&3;
            uint32_t doff = (uint32_t)(r*LDS_PAD + cg*8)*2;
            size_t ga = (size_t)(row0+r)*K + k0 + cg*8;
            size_t gb = (size_t)(col0+r)*K + k0 + cg*8;
            cpasync16(sb + 0*TILE_E*2 + doff, Ah + ga);
            cpasync16(sb + 1*TILE_E*2 + doff, Al + ga);
            cpasync16(sb + 2*TILE_E*2 + doff, Bh + gb);
            cpasync16(sb + 3*TILE_E*2 + doff, Bl + gb);
        }
        asm volatile("cp.async.commit_group;");
    };

    issue(0, 0);
    for (int c=0; c<NC; c++){
        if (c+1 < NC){
            issue(c+1, (c+1)&1);
            asm volatile("cp.async.wait_group 1;");
        } else {
            asm volatile("cp.async.wait_group 0;");
        }
        __syncthreads();

        uint32_t sb = sbase + (uint32_t)(c&1)*BUF_E*2;
        uint32_t aH = sb, aL = sb+TILE_E*2, bH = sb+2*TILE_E*2, bL = sb+3*TILE_E*2;
        #pragma unroll
        for (int ks=0; ks<2; ks++){
            uint32_t ah[4][4], al[4][4], bh[4][2], bl[4][2];
            #pragma unroll
            for (int i=0;i<4;i++){
                uint32_t ra = (uint32_t)((wm*64 + i*16 + arow)*LDS_PAD + ks*16 + akk)*2;
                LDMX4(ah[i], aH+ra);
                LDMX4(al[i], aL+ra);
            }
            #pragma unroll
            for (int j2=0;j2<2;j2++){
                uint32_t rb = (uint32_t)((wn*32 + j2*16 + bn)*LDS_PAD + ks*16 + bk)*2;
                uint32_t r1[4], r2[4];
                LDMX4(r1, bH+rb);
                bh[2*j2][0]=r1[0]; bh[2*j2][1]=r1[1]; bh[2*j2+1][0]=r1[2]; bh[2*j2+1][1]=r1[3];
                LDMX4(r2, bL+rb);
                bl[2*j2][0]=r2[0]; bl[2*j2][1]=r2[1]; bl[2*j2+1][0]=r2[2]; bl[2*j2+1][1]=r2[3];
            }
            // term-major ordering: 16 independent MMAs between accumulator reuse
            #pragma unroll
            for (int i=0;i<4;i++)
                #pragma unroll
                for (int j=0;j<4;j++)
                    MMA16816(acc[i][j], ah[i], bh[j]);
            #pragma unroll
            for (int i=0;i<4;i++)
                #pragma unroll
                for (int j=0;j<4;j++)
                    MMA16816(acc[i][j], ah[i], bl[j]);
            #pragma unroll
            for (int i=0;i<4;i++)
                #pragma unroll
                for (int j=0;j<4;j++)
                    MMA16816(acc[i][j], al[i], bh[j]);
        }
        __syncthreads();
    }

    if (TRANS_OUT){
        // stage per-warp 64x32 into smem as [col][row], then coalesced column writes
        float* ep = (float*)smem + (size_t)wid*(32*65);
        #pragma unroll
        for (int i=0;i<4;i++)
            #pragma unroll
            for (int j=0;j<4;j++){
                int rl = i*16 + (lane>>2);
                int cl = j*8 + 2*(lane&3);
                ep[cl*65 + rl]        = acc[i][j][0];
                ep[(cl+1)*65 + rl]    = acc[i][j][1];
                ep[cl*65 + rl + 8]    = acc[i][j][2];
                ep[(cl+1)*65 + rl + 8]= acc[i][j][3];
            }
        __syncwarp();
        #pragma unroll 4
        for (int cc=0; cc<32; cc++){
            int colg = col0 + wn*32 + cc;
            float* dst = C + (size_t)colg*M + row0 + wm*64;
            dst[lane]      = ep[cc*65 + lane];
            dst[lane + 32] = ep[cc*65 + lane + 32];
        }
    } else {
        #pragma unroll
        for (int i=0;i<4;i++)
            #pragma unroll
            for (int j=0;j<4;j++){
                int rg = row0 + wm*64 + i*16 + (lane>>2);
                int cg = col0 + wn*32 + j*8 + 2*(lane&3);
                C[(size_t)rg*N + cg]       = acc[i][j][0];
                C[(size_t)rg*N + cg + 1]   = acc[i][j][1];
                C[(size_t)(rg+8)*N + cg]   = acc[i][j][2];
                C[(size_t)(rg+8)*N + cg+1] = acc[i][j][3];
            }
    }
}

// ---------------- mix: deltaT = lam*(W^T a - a) ----------------
__global__ __launch_bounds__(256) void mix_kernel(int hd){
    __shared__ float sC[NROW];
    __shared__ float sW[NW*NW];
    int m = blockIdx.x, e = blockIdx.y, t = threadIdx.x;
    size_t wb = ((size_t)(hd*NE+e)*NM + m)*NW*NW;
    #pragma unroll
    for (int tt=0; tt<2; tt++){
        const float* Wp = tt ? g_Wt2 : g_Wt1;
        int col = (e*2+tt)*NM + m;
        __syncthreads();
        for (int i=t;i<NROW;i+=256) sC[i] = g_coefT[(size_t)col*NROW + i];
        for (int i=t;i<NW*NW;i+=256) sW[i] = Wp[wb + i];
        __syncthreads();
        for (int oi=t; oi<NROW; oi+=256){
            int b = oi>>6, o = oi&63;
            float acc = -sC[oi];
            const float* cbp = &sC[b*NW];
            #pragma unroll 8
            for (int i=0;i<NW;i++) acc += cbp[i]*sW[i*NW+o];
            g_deltaT[(size_t)col*NROW + oi] = acc * g_lam[(hd*NB+b)*NE+e];
        }
    }
}

// ---------------- combine ----------------
__global__ __launch_bounds__(256) void combine_kernel(const float* __restrict__ hin,
        const float* __restrict__ corr, const float* __restrict__ ww,
        const float* __restrict__ wb, float* __restrict__ hout, int hd){
    __shared__ float sH[NW][65];
    __shared__ float sW[NW][NW];
    int b = blockIdx.y, x0 = blockIdx.x*64, t = threadIdx.x;
    for (int idx=t; idx<NW*64; idx+=256){
        int c=idx>>6, xx=idx&63;
        sH[c][xx] = hin[(b*NW+c)*NS + x0+xx];
    }
    for (int idx=t; idx<NW*NW; idx+=256) sW[idx>>6][idx&63] = ww[hd*NW*NW+idx];
    __syncthreads();
    for (int idx=t; idx<NW*64; idx+=256){
        int c=idx>>6, xx=idx&63;
        float accv = wb[hd*NW+c];
        #pragma unroll 8
        for (int k=0;k<NW;k++) accv += sW[c][k]*sH[k][xx];
        int gi = (b*NW+c)*NS + x0+xx;
        float pre = sH[c][xx] + corr[gi] + accv;
        hout[gi] = mishf(pre);
    }
}

// ---------------- head ----------------
__global__ __launch_bounds__(256) void head_kernel(const float* __restrict__ hin,
        const float* __restrict__ fc2_w, const float* __restrict__ fc2_b,
        const float* __restrict__ fc3_w, const float* __restrict__ fc3_b,
        float* __restrict__ out){
    __shared__ float sWT[NW*128];
    __shared__ float sH[8][NW];
    __shared__ float sb2[128], sw3[128];
    int b = blockIdx.y, x0 = blockIdx.x*8, t = threadIdx.x;
    for (int idx=t; idx<128*NW; idx+=256){
        int j=idx>>6, k=idx&63;
        sWT[k*128+j] = fc2_w[idx];
    }
    if (t<128){ sb2[t]=fc2_b[t]; sw3[t]=fc3_w[t]; }
    for (int idx=t; idx<8*NW; idx+=256){
        int c = idx>>3, xx = idx&7;
        sH[xx][c] = hin[(b*NW+c)*NS + x0+xx];
    }
    __syncthreads();
    int w = t>>5, lane = t&31;
    const float* hrow = sH[w];
    float partial = 0.f;
    #pragma unroll
    for (int jj=0;jj<4;jj++){
        int j = lane + jj*32;
        float accv = sb2[j];
        #pragma unroll 8
        for (int k=0;k<NW;k++) accv += sWT[k*128+j]*hrow[k];
        partial += sw3[j]*mishf(accv);
    }
    #pragma unroll
    for (int off=16;off;off>>=1) partial += __shfl_xor_sync(0xFFFFFFFFu, partial, off);
    if (lane==0) out[b*NS + x0 + w] = partial + fc3_b[0];
}

// ---------------- host: Daubechies filters ----------------
static double binom_d(int n, int k){
    double r = 1.0;
    for (int i=1;i<=k;i++) r = r*(double)(n-k+i)/(double)i;
    return r;
}
static void db_lo(int N, double* h20){
    for (int i=0;i<LF;i++) h20[i]=0.0;
    int L = 2*N;
    std::vector<std::complex<double>> ch(N+1);
    double p2 = std::pow(0.5, N);
    for (int i=0;i<=N;i++) ch[i] = binom_d(N,i)*p2;
    if (N > 1){
        std::vector<double> Q(2*N-1, 0.0);
        const double base[3] = {-0.25, 0.5, -0.25};
        for (int k=0;k<N;k++){
            std::vector<double> tt(1, 1.0);
            for (int p=0;p<k;p++){
                std::vector<double> r2(tt.size()+2, 0.0);
                for (size_t a=0;a<tt.size();a++)
                    for (int bb=0;bb<3;bb++) r2[a+bb] += tt[a]*base[bb];
                tt.swap(r2);
            }
            double pyk = binom_d(N-1+k, k);
            for (size_t j=0;j<tt.size();j++) Q[N-1-k+j] += pyk*tt[j];
        }
        int deg = 2*N-2;
        std::vector<std::complex<double>> c(deg);
        for (int mth=0;mth<deg;mth++) c[mth] = Q[mth]/Q[deg];
        std::vector<std::complex<double>> z(deg);
        std::complex<double> seed(0.4,0.9), curz(1.0,0.0);
        for (int i=0;i<deg;i++){ curz *= seed; z[i]=curz; }
        for (int it=0; it<2000; it++){
            for (int i=0;i<deg;i++){
                std::complex<double> pv(1.0,0.0);
                for (int mth=deg-1;mth>=0;mth--) pv = pv*z[i] + c[mth];
                std::complex<double> den(1.0,0.0);
                for (int j=0;j<deg;j++) if (j!=i) den *= (z[i]-z[j]);
                if (std::abs(den) < 1e-300) den = 1e-300;
                z[i] -= pv/den;
            }
        }
        for (int i=0;i<deg;i++){
            if (std::abs(z[i]) < 1.0){
                std::complex<double> r = z[i];
                std::complex<double> inv = 1.0/(std::complex<double>(1.0,0.0) - r);
                std::vector<std::complex<double>> nh(ch.size()+1, std::complex<double>(0.0,0.0));
                for (size_t a=0;a<ch.size();a++){
                    nh[a]   += ch[a]*(-r)*inv;
                    nh[a+1] += ch[a]*inv;
                }
                ch.swap(nh);
            }
        }
    }
    double s2 = std::sqrt(2.0);
    for (int i=0;i<L && i<(int)ch.size() && i<LF;i++) h20[i] = ch[i].real()*s2;
}
static Filters make_filters(){
    Filters F;
    for (int e=0;e<NE;e++){
        int N = e+1, L = 2*N;
        double h[LF];
        db_lo(N, h);
        for (int tp=0;tp<LF;tp++){
            F.f[e][0][tp] = (float)h[tp];
            F.f[e][1][tp] = (tp < L) ? (float)(h[L-1-tp] * ((tp&1)?-1.0:1.0)) : 0.f;
        }
    }
    return F;
}

// ---------------- launch ----------------
extern "C" void kernel_launch(void* const* d_in, const int* in_sizes, int n_in,
                              void* d_out, int out_size){
    const float* x     = (const float*)d_in[0];
    const float* label = (const float*)d_in[1];
    const float* fc0_w = (const float*)d_in[2];
    const float* fc0_b = (const float*)d_in[3];
    const float* fc1_w = (const float*)d_in[4];
    const float* fc1_b = (const float*)d_in[5];
    const float* gwl   = (const float*)d_in[6];
    const float* gbl   = (const float*)d_in[7];
    const float* gwg   = (const float*)d_in[8];
    const float* gbg   = (const float*)d_in[9];
    const float* ew1   = (const float*)d_in[10];
    const float* ew2   = (const float*)d_in[11];
    const float* ww    = (const float*)d_in[12];
    const float* wb    = (const float*)d_in[13];
    const float* fc2_w = (const float*)d_in[14];
    const float* fc2_b = (const float*)d_in[15];
    const float* fc3_w = (const float*)d_in[16];
    const float* fc3_b = (const float*)d_in[17];

    Filters F = make_filters();

    float *dA, *dB, *dCorr, *dCoefT;
    __nv_bfloat16 *dHhi,*dHlo,*dDhi,*dDlo,*dStHi,*dStLo,*dSxHi,*dSxLo;
    cudaGetSymbolAddress((void**)&dA,    g_bufA);
    cudaGetSymbolAddress((void**)&dB,    g_bufB);
    cudaGetSymbolAddress((void**)&dCorr, g_corr);
    cudaGetSymbolAddress((void**)&dCoefT,g_coefT);
    cudaGetSymbolAddress((void**)&dHhi,  g_Hhi);
    cudaGetSymbolAddress((void**)&dHlo,  g_Hlo);
    cudaGetSymbolAddress((void**)&dDhi,  g_Dhi);
    cudaGetSymbolAddress((void**)&dDlo,  g_Dlo);
    cudaGetSymbolAddress((void**)&dStHi, g_StHi);
    cudaGetSymbolAddress((void**)&dStLo, g_StLo);
    cudaGetSymbolAddress((void**)&dSxHi, g_SxHi);
    cudaGetSymbolAddress((void**)&dSxLo, g_SxLo);

    cudaFuncSetAttribute(gemm_kernel<0>, cudaFuncAttributeMaxDynamicSharedMemorySize, GEMM_SMEM);
    cudaFuncSetAttribute(gemm_kernel<1>, cudaFuncAttributeMaxDynamicSharedMemorySize, GEMM_SMEM);

    build_syn_kernel<<<NE*2*NM, 128>>>(F);
    transw_kernel<<<dim3(64, NHID*NE), 256>>>(ew1, ew2);
    prep_lift_kernel<<<1, 64>>>(fc0_w, fc0_b, fc1_w, fc1_b);
    lift_kernel<<<(NROW*NS)/256, 256>>>(x);
    xf_kernel<<<NROW, 256>>>(dA);
    gate_kernel<<<1, 256>>>(label, gwl, gbl, gwg, gbg);

    float* cur = dA; float* nxt = dB;
    for (int hd=0; hd<NHID; hd++){
        split_kernel<<<(NROW*NS/4)/256, 256>>>(cur, dHhi, dHlo, NROW*NS/4);
        gemm_kernel<1><<<dim3(NCOL/128, NROW/128), 256, GEMM_SMEM>>>(
            dHhi, dHlo, dStHi, dStLo, dCoefT, NROW, NCOL, NS);
        mix_kernel<<<dim3(NM, NE), 256>>>(hd);
        tsplit_kernel<<<dim3(NCOL/32, NROW/32), 256>>>();
        gemm_kernel<0><<<dim3(NS/128, NROW/128), 256, GEMM_SMEM>>>(
            dDhi, dDlo, dSxHi, dSxLo, dCorr, NROW, NS, NCOL);
        combine_kernel<<<dim3(NS/64, NB), 256>>>(cur, dCorr, ww, wb, nxt, hd);
        float* tp = cur; cur = nxt; nxt = tp;
    }
    head_kernel<<<dim3(NS/8, NB), 256>>>(cur, fc2_w, fc2_b, fc3_w, fc3_b, (float*)d_out);
}

// round 5
// speedup vs baseline: 2.5973x; 1.1914x over previous
#include <cuda_runtime.h>
#include <cuda_fp16.h>
#include <cmath>
#include <vector>
#include <complex>
#include <cstdint>

// ---------------- problem constants ----------------
#define NE   10
#define LF   20
#define NB   32
#define NW   64
#define NS   1024
#define NM   64
#define NHID 4
#define NROW (NB*NW)     // 2048
#define NCOL (NE*2*NM)   // 1280

// ---------------- device scratch ----------------
__device__ float g_bufA [NROW*NS];
__device__ float g_bufB [NROW*NS];
__device__ float g_corr [NROW*NS];
__device__ float g_coefT[NCOL*NROW];      // [col][row]
__device__ float g_deltaT[NCOL*NROW];     // [col][row]
__device__ __half g_Hhi[NROW*NS],  g_Hlo[NROW*NS];    // h split, row-major [row][x]
__device__ __half g_Dhi[NROW*NCOL],g_Dlo[NROW*NCOL];  // delta split, [row][col]
__device__ __half g_StH[NCOL*NS];                     // S^T  [col][x]  (single fp16)
__device__ __half g_SxH[NS*NCOL];                     // S    [x][col]  (single fp16)
__device__ float g_Wt1[(size_t)NHID*NE*NM*NW*NW];     // [hd][e][m][i][o]
__device__ float g_Wt2[(size_t)NHID*NE*NM*NW*NW];
__device__ float g_xf [NROW];
__device__ float g_lam[NHID*NB*NE];
__device__ float g_A2 [NW*2];
__device__ float g_Bc [NW];

struct Filters { float f[NE][2][LF]; };

__device__ __forceinline__ float mishf(float x){
    float sp = (x > 20.f) ? x : log1pf(expf(x));
    return x * tanhf(sp);
}

__device__ __forceinline__ uint32_t s2u(const void* p){
    uint32_t a;
    asm("{ .reg .u64 t; cvta.to.shared.u64 t, %1; cvt.u32.u64 %0, t; }" : "=r"(a) : "l"(p));
    return a;
}

__device__ __forceinline__ void cpasync16(uint32_t d, const void* g){
    asm volatile("cp.async.cg.shared.global [%0], [%1], 16;" :: "r"(d), "l"(g));
}

#define LDMX4(r, a) \
    asm volatile("ldmatrix.sync.aligned.m8n8.x4.shared.b16 {%0,%1,%2,%3}, [%4];" \
        : "=r"((r)[0]),"=r"((r)[1]),"=r"((r)[2]),"=r"((r)[3]) : "r"(a))

#define MMA16816(c, a, b) \
    asm volatile("mma.sync.aligned.m16n8k16.row.col.f32.f16.f16.f32 " \
        "{%0,%1,%2,%3}, {%4,%5,%6,%7}, {%8,%9}, {%0,%1,%2,%3};" \
        : "+f"((c)[0]),"+f"((c)[1]),"+f"((c)[2]),"+f"((c)[3]) \
        : "r"((a)[0]),"r"((a)[1]),"r"((a)[2]),"r"((a)[3]), "r"((b)[0]),"r"((b)[1]))

// ---------------- build synthesis matrix (both layouts, fp16) ----------------
__global__ __launch_bounds__(128) void build_syn_kernel(Filters F){
    __shared__ float b0[NS], b1[NS];
    int bid = blockIdx.x;
    int m = bid & 63, tt = (bid>>6)&1, e = bid>>7;
    int t = threadIdx.x;
    float* cur = b0; float* nxt = b1;
    for (int i=t;i<64;i+=128) cur[i] = (i==m)?1.f:0.f;
    __syncthreads();
    int n_in = 64;
    #pragma unroll
    for (int s=0;s<4;s++){
        int n_out = n_in<<1;
        const float* f = (s==0 && tt==1) ? F.f[e][1] : F.f[e][0];
        for (int x=t;x<n_out;x+=128){
            int j0 = x>>1, par = x&1;
            float acc = 0.f;
            #pragma unroll
            for (int u=0;u<10;u++){
                int j = j0-u; if (j<0) j += n_in;
                acc += cur[j]*f[par+2*u];
            }
            nxt[x]=acc;
        }
        __syncthreads();
        float* tp=cur; cur=nxt; nxt=tp;
        n_in = n_out;
    }
    int col = (e*2+tt)*64+m;
    for (int x=t;x<NS;x+=128){
        __half h = __float2half_rn(cur[x]);
        g_StH[(size_t)col*NS + x] = h;
        g_SxH[(size_t)x*NCOL + col] = h;
    }
}

// ---------------- transpose expert weights -> [hd][e][m][i][o] ----------------
__global__ __launch_bounds__(256) void transw_kernel(const float* __restrict__ w1,
                                                     const float* __restrict__ w2){
    __shared__ float sT[64][65];
    int i  = blockIdx.x;
    int he = blockIdx.y;
    size_t inb  = ((size_t)he*NW + i)*NW*NM;
    size_t outb = (size_t)he*NM*NW*NW;
    int t = threadIdx.x;
    for (int s=0;s<2;s++){
        const float* W = s ? w2 : w1;
        float* O = s ? g_Wt2 : g_Wt1;
        __syncthreads();
        #pragma unroll
        for (int k=0;k<16;k++){ int idx=t+k*256; int o=idx>>6, m=idx&63; sT[o][m]=W[inb + (size_t)o*NM + m]; }
        __syncthreads();
        #pragma unroll
        for (int k=0;k<16;k++){ int idx=t+k*256; int m=idx>>6, o=idx&63; O[outb + ((size_t)m*NW + i)*NW + o] = sT[o][m]; }
    }
}

// ---------------- lift: writes fp32 h AND fp16 hi/lo ----------------
__global__ void prep_lift_kernel(const float* __restrict__ fc0_w, const float* __restrict__ fc0_b,
                                 const float* __restrict__ fc1_w, const float* __restrict__ fc1_b){
    int c = threadIdx.x;
    if (c >= NW) return;
    float a0=0.f,a1=0.f,bb=0.f;
    for (int k=0;k<NW;k++){
        float w = fc1_w[c*NW+k];
        a0 += w*fc0_w[k*2+0];
        a1 += w*fc0_w[k*2+1];
        bb += w*fc0_b[k];
    }
    g_A2[c*2]=a0; g_A2[c*2+1]=a1; g_Bc[c]=bb+fc1_b[c];
}

__global__ __launch_bounds__(256) void lift_kernel(const float* __restrict__ x){
    int i = blockIdx.x*256 + threadIdx.x;
    if (i >= NROW*NS/4) return;
    int base = i*4;
    int xp = base & (NS-1);
    int c  = (base>>10)&63;
    int b  = base>>16;
    float4 xv = *(const float4*)&x[b*NS+xp];
    float a0 = g_A2[c*2], a1 = g_A2[c*2+1], bc = g_Bc[c];
    const float inv = 1.f/1023.f;
    float v0 = a0*xv.x + a1*((float)(xp+0)*inv) + bc;
    float v1 = a0*xv.y + a1*((float)(xp+1)*inv) + bc;
    float v2 = a0*xv.z + a1*((float)(xp+2)*inv) + bc;
    float v3 = a0*xv.w + a1*((float)(xp+3)*inv) + bc;
    *(float4*)&g_bufA[base] = make_float4(v0,v1,v2,v3);
    __half h0=__float2half_rn(v0), h1=__float2half_rn(v1);
    __half h2=__float2half_rn(v2), h3=__float2half_rn(v3);
    __half l0=__float2half_rn(v0-__half2float(h0));
    __half l1=__float2half_rn(v1-__half2float(h1));
    __half l2=__float2half_rn(v2-__half2float(h2));
    __half l3=__float2half_rn(v3-__half2float(h3));
    ((__half2*)g_Hhi)[i*2+0] = __halves2half2(h0,h1);
    ((__half2*)g_Hhi)[i*2+1] = __halves2half2(h2,h3);
    ((__half2*)g_Hlo)[i*2+0] = __halves2half2(l0,l1);
    ((__half2*)g_Hlo)[i*2+1] = __halves2half2(l2,l3);
}

// ---------------- xf ----------------
__global__ __launch_bounds__(256) void xf_kernel(const float* __restrict__ h){
    __shared__ float red[256];
    int r = blockIdx.x, t = threadIdx.x;
    float s = 0.f;
    for (int xp=t; xp<NS; xp+=256) s += h[r*NS+xp];
    red[t]=s; __syncthreads();
    for (int o=128;o;o>>=1){ if (t<o) red[t]+=red[t+o]; __syncthreads(); }
    if (t==0) g_xf[r] = red[0]*(1.f/1024.f);
}

// ---------------- gates ----------------
__global__ __launch_bounds__(256) void gate_kernel(const float* __restrict__ label,
        const float* __restrict__ wl, const float* __restrict__ bl,
        const float* __restrict__ wg, const float* __restrict__ bg){
    __shared__ float s_lf[NHID][32];
    __shared__ float s_logit[NHID][NB][NE];
    __shared__ float s_xf[NB][NW];
    __shared__ float s_labsum;
    int t = threadIdx.x;
    if (t==0){ float s=0.f; for(int l=0;l<10;l++) s+=label[l]; s_labsum=s; }
    for (int idx=t; idx<NB*NW; idx+=256) s_xf[idx>>6][idx&63] = g_xf[idx];
    __syncthreads();
    if (t < 128){
        int hd=t>>5, o=t&31;
        float s=0.f;
        for (int c=0;c<NW;c++) s += wl[(hd*32+o)*NW+c];
        s_lf[hd][o] = s*s_labsum*0.1f + bl[hd*32+o];
    }
    __syncthreads();
    for (int idx=t; idx<NHID*NB*NE; idx+=256){
        int hd = idx/(NB*NE); int r = idx%(NB*NE); int b=r/NE, e=r%NE;
        const float* w = &wg[(hd*NE+e)*96];
        float s = bg[hd*NE+e];
        for (int c=0;c<NW;c++) s += s_xf[b][c]*w[c];
        for (int o=0;o<32;o++)  s += s_lf[hd][o]*w[64+o];
        s_logit[hd][b][e]=s;
    }
    __syncthreads();
    if (t < 128){
        int hd=t>>5, b=t&31;
        float mx=-1e30f;
        for (int e=0;e<NE;e++) mx = fmaxf(mx, s_logit[hd][b][e]);
        float ex[NE]; float sum=0.f;
        for (int e=0;e<NE;e++){ ex[e]=expf(s_logit[hd][b][e]-mx); sum+=ex[e]; }
        float inv = 1.f/sum;
        for (int e=0;e<NE;e++) g_lam[(hd*NB+b)*NE+e] = ex[e]*inv;
    }
}

// ---------------- transpose deltaT [col][row] -> Dhi/Dlo [row][col] fp16 ----------------
__global__ __launch_bounds__(256) void tsplit_kernel(){
    __shared__ float sT[32][33];
    int c0 = blockIdx.x*32, r0 = blockIdx.y*32;
    int t = threadIdx.x;
    #pragma unroll
    for (int i=0;i<4;i++){
        int idx=t+i*256; int cc=idx>>5, rr=idx&31;
        sT[cc][rr] = g_deltaT[(size_t)(c0+cc)*NROW + r0+rr];
    }
    __syncthreads();
    #pragma unroll
    for (int i=0;i<2;i++){
        int idx=t+i*256; int rr=idx>>4, c2=(idx&15)*2;
        float v0=sT[c2][rr], v1=sT[c2+1][rr];
        __half h0=__float2half_rn(v0), h1=__float2half_rn(v1);
        __half l0=__float2half_rn(v0-__half2float(h0));
        __half l1=__float2half_rn(v1-__half2float(h1));
        size_t o = (size_t)(r0+rr)*NCOL + c0+c2;
        *(__half2*)&g_Dhi[o] = __halves2half2(h0,h1);
        *(__half2*)&g_Dlo[o] = __halves2half2(l0,l1);
    }
}

// ---------------- mma.sync 2-term fp16 GEMM ----------------
// C[M][N] = sum_k A[m][k]*B[n][k], A = Ah + Al (exact fp16 split), B fp16.
// TRANS_OUT=1: write C^T (C[n][m], ld=M). Else C[m][n], ld=N.
#define LDS_PAD 40
#define TILE_B  (128*LDS_PAD*2)        // 10240 bytes per tile
#define BUF_B   (3*TILE_B)             // 30720 bytes per buffer
#define GEMM_SMEM 66560                // max(2*BUF_B=61440, epilogue 8*32*65*4=66560)

template<int TRANS_OUT>
__global__ __launch_bounds__(256,2) void gemm_kernel(
        const __half* __restrict__ Ah, const __half* __restrict__ Al,
        const __half* __restrict__ B,
        float* __restrict__ C, int M, int N, int K){
    extern __shared__ char smem[];
    uint32_t sbase = s2u(smem);
    int t = threadIdx.x, lane = t&31, wid = t>>5;
    int wm = wid>>2, wn = wid&3;
    int row0 = blockIdx.y*128, col0 = blockIdx.x*128;

    float acc[4][4][4];
    #pragma unroll
    for (int i=0;i<4;i++)
        #pragma unroll
        for (int j=0;j<4;j++)
            #pragma unroll
            for (int r=0;r<4;r++) acc[i][j][r]=0.f;

    int arow = lane & 15;           int akk = (lane>>4)<<3;
    int bn   = (lane&7) + ((lane>>4)<<3);
    int bk   = lane & 8;

    int NC = K >> 5;

    auto issue = [&](int c, int buf){
        int k0 = c<<5;
        uint32_t sb = sbase + (uint32_t)buf*BUF_B;
        #pragma unroll
        for (int i=0;i<2;i++){
            int idx = t + i*256;
            int r = idx>>2, cg = idx&3;
            uint32_t doff = (uint32_t)(r*LDS_PAD + cg*8)*2;
            size_t ga = (size_t)(row0+r)*K + k0 + cg*8;
            size_t gb = (size_t)(col0+r)*K + k0 + cg*8;
            cpasync16(sb + 0*TILE_B + doff, Ah + ga);
            cpasync16(sb + 1*TILE_B + doff, Al + ga);
            cpasync16(sb + 2*TILE_B + doff, B  + gb);
        }
        asm volatile("cp.async.commit_group;");
    };

    issue(0, 0);
    for (int c=0; c<NC; c++){
        if (c+1 < NC){
            issue(c+1, (c+1)&1);
            asm volatile("cp.async.wait_group 1;");
        } else {
            asm volatile("cp.async.wait_group 0;");
        }
        __syncthreads();

        uint32_t sb = sbase + (uint32_t)(c&1)*BUF_B;
        uint32_t aH = sb, aL = sb+TILE_B, bB = sb+2*TILE_B;
        #pragma unroll
        for (int ks=0; ks<2; ks++){
            uint32_t ah[4][4], al[4][4], bf[4][2];
            #pragma unroll
            for (int i=0;i<4;i++){
                uint32_t ra = (uint32_t)((wm*64 + i*16 + arow)*LDS_PAD + ks*16 + akk)*2;
                LDMX4(ah[i], aH+ra);
                LDMX4(al[i], aL+ra);
            }
            #pragma unroll
            for (int j2=0;j2<2;j2++){
                uint32_t rb = (uint32_t)((wn*32 + j2*16 + bn)*LDS_PAD + ks*16 + bk)*2;
                uint32_t r1[4];
                LDMX4(r1, bB+rb);
                bf[2*j2][0]=r1[0]; bf[2*j2][1]=r1[1]; bf[2*j2+1][0]=r1[2]; bf[2*j2+1][1]=r1[3];
            }
            // term-major: 16 independent MMAs between accumulator reuse
            #pragma unroll
            for (int i=0;i<4;i++)
                #pragma unroll
                for (int j=0;j<4;j++)
                    MMA16816(acc[i][j], ah[i], bf[j]);
            #pragma unroll
            for (int i=0;i<4;i++)
                #pragma unroll
                for (int j=0;j<4;j++)
                    MMA16816(acc[i][j], al[i], bf[j]);
        }
        __syncthreads();
    }

    if (TRANS_OUT){
        float* ep = (float*)smem + (size_t)wid*(32*65);
        #pragma unroll
        for (int i=0;i<4;i++)
            #pragma unroll
            for (int j=0;j<4;j++){
                int rl = i*16 + (lane>>2);
                int cl = j*8 + 2*(lane&3);
                ep[cl*65 + rl]        = acc[i][j][0];
                ep[(cl+1)*65 + rl]    = acc[i][j][1];
                ep[cl*65 + rl + 8]    = acc[i][j][2];
                ep[(cl+1)*65 + rl + 8]= acc[i][j][3];
            }
        __syncwarp();
        #pragma unroll 4
        for (int cc=0; cc<32; cc++){
            int colg = col0 + wn*32 + cc;
            float* dst = C + (size_t)colg*M + row0 + wm*64;
            dst[lane]      = ep[cc*65 + lane];
            dst[lane + 32] = ep[cc*65 + lane + 32];
        }
    } else {
        #pragma unroll
        for (int i=0;i<4;i++)
            #pragma unroll
            for (int j=0;j<4;j++){
                int rg = row0 + wm*64 + i*16 + (lane>>2);
                int cg = col0 + wn*32 + j*8 + 2*(lane&3);
                C[(size_t)rg*N + cg]       = acc[i][j][0];
                C[(size_t)rg*N + cg + 1]   = acc[i][j][1];
                C[(size_t)(rg+8)*N + cg]   = acc[i][j][2];
                C[(size_t)(rg+8)*N + cg+1] = acc[i][j][3];
            }
    }
}

// ---------------- mix: deltaT = lam*(W^T a - a) ----------------
__global__ __launch_bounds__(256) void mix_kernel(int hd){
    __shared__ float sC[NROW];
    __shared__ float sW[NW*NW];
    int m = blockIdx.x, e = blockIdx.y, t = threadIdx.x;
    size_t wb = ((size_t)(hd*NE+e)*NM + m)*NW*NW;
    #pragma unroll
    for (int tt=0; tt<2; tt++){
        const float* Wp = tt ? g_Wt2 : g_Wt1;
        int col = (e*2+tt)*NM + m;
        __syncthreads();
        for (int i=t;i<NROW;i+=256) sC[i] = g_coefT[(size_t)col*NROW + i];
        for (int i=t;i<NW*NW;i+=256) sW[i] = Wp[wb + i];
        __syncthreads();
        for (int oi=t; oi<NROW; oi+=256){
            int b = oi>>6, o = oi&63;
            float acc = -sC[oi];
            const float* cbp = &sC[b*NW];
            #pragma unroll 8
            for (int i=0;i<NW;i++) acc += cbp[i]*sW[i*NW+o];
            g_deltaT[(size_t)col*NROW + oi] = acc * g_lam[(hd*NB+b)*NE+e];
        }
    }
}

// ---------------- combine: also emits fp16 hi/lo of h_out ----------------
__global__ __launch_bounds__(256) void combine_kernel(const float* __restrict__ hin,
        const float* __restrict__ corr, const float* __restrict__ ww,
        const float* __restrict__ wb, float* __restrict__ hout, int hd){
    __shared__ float sH[NW][65];
    __shared__ float sW[NW][NW];
    int b = blockIdx.y, x0 = blockIdx.x*64, t = threadIdx.x;
    for (int idx=t; idx<NW*64; idx+=256){
        int c=idx>>6, xx=idx&63;
        sH[c][xx] = hin[(b*NW+c)*NS + x0+xx];
    }
    for (int idx=t; idx<NW*NW; idx+=256) sW[idx>>6][idx&63] = ww[hd*NW*NW+idx];
    __syncthreads();
    for (int idx=t; idx<NW*64; idx+=256){
        int c=idx>>6, xx=idx&63;
        float accv = wb[hd*NW+c];
        #pragma unroll 8
        for (int k=0;k<NW;k++) accv += sW[c][k]*sH[k][xx];
        int gi = (b*NW+c)*NS + x0+xx;
        float pre = sH[c][xx] + corr[gi] + accv;
        float hv = mishf(pre);
        hout[gi] = hv;
        __half hh = __float2half_rn(hv);
        g_Hhi[gi] = hh;
        g_Hlo[gi] = __float2half_rn(hv - __half2float(hh));
    }
}

// ---------------- head ----------------
__global__ __launch_bounds__(256) void head_kernel(const float* __restrict__ hin,
        const float* __restrict__ fc2_w, const float* __restrict__ fc2_b,
        const float* __restrict__ fc3_w, const float* __restrict__ fc3_b,
        float* __restrict__ out){
    __shared__ float sWT[NW*128];
    __shared__ float sH[8][NW];
    __shared__ float sb2[128], sw3[128];
    int b = blockIdx.y, x0 = blockIdx.x*8, t = threadIdx.x;
    for (int idx=t; idx<128*NW; idx+=256){
        int j=idx>>6, k=idx&63;
        sWT[k*128+j] = fc2_w[idx];
    }
    if (t<128){ sb2[t]=fc2_b[t]; sw3[t]=fc3_w[t]; }
    for (int idx=t; idx<8*NW; idx+=256){
        int c = idx>>3, xx = idx&7;
        sH[xx][c] = hin[(b*NW+c)*NS + x0+xx];
    }
    __syncthreads();
    int w = t>>5, lane = t&31;
    const float* hrow = sH[w];
    float partial = 0.f;
    #pragma unroll
    for (int jj=0;jj<4;jj++){
        int j = lane + jj*32;
        float accv = sb2[j];
        #pragma unroll 8
        for (int k=0;k<NW;k++) accv += sWT[k*128+j]*hrow[k];
        partial += sw3[j]*mishf(accv);
    }
    #pragma unroll
    for (int off=16;off;off>>=1) partial += __shfl_xor_sync(0xFFFFFFFFu, partial, off);
    if (lane==0) out[b*NS + x0 + w] = partial + fc3_b[0];
}

// ---------------- host: Daubechies filters ----------------
static double binom_d(int n, int k){
    double r = 1.0;
    for (int i=1;i<=k;i++) r = r*(double)(n-k+i)/(double)i;
    return r;
}
static void db_lo(int N, double* h20){
    for (int i=0;i<LF;i++) h20[i]=0.0;
    int L = 2*N;
    std::vector<std::complex<double>> ch(N+1);
    double p2 = std::pow(0.5, N);
    for (int i=0;i<=N;i++) ch[i] = binom_d(N,i)*p2;
    if (N > 1){
        std::vector<double> Q(2*N-1, 0.0);
        const double base[3] = {-0.25, 0.5, -0.25};
        for (int k=0;k<N;k++){
            std::vector<double> tt(1, 1.0);
            for (int p=0;p<k;p++){
                std::vector<double> r2(tt.size()+2, 0.0);
                for (size_t a=0;a<tt.size();a++)
                    for (int bb=0;bb<3;bb++) r2[a+bb] += tt[a]*base[bb];
                tt.swap(r2);
            }
            double pyk = binom_d(N-1+k, k);
            for (size_t j=0;j<tt.size();j++) Q[N-1-k+j] += pyk*tt[j];
        }
        int deg = 2*N-2;
        std::vector<std::complex<double>> c(deg);
        for (int mth=0;mth<deg;mth++) c[mth] = Q[mth]/Q[deg];
        std::vector<std::complex<double>> z(deg);
        std::complex<double> seed(0.4,0.9), curz(1.0,0.0);
        for (int i=0;i<deg;i++){ curz *= seed; z[i]=curz; }
        for (int it=0; it<2000; it++){
            for (int i=0;i<deg;i++){
                std::complex<double> pv(1.0,0.0);
                for (int mth=deg-1;mth>=0;mth--) pv = pv*z[i] + c[mth];
                std::complex<double> den(1.0,0.0);
                for (int j=0;j<deg;j++) if (j!=i) den *= (z[i]-z[j]);
                if (std::abs(den) < 1e-300) den = 1e-300;
                z[i] -= pv/den;
            }
        }
        for (int i=0;i<deg;i++){
            if (std::abs(z[i]) < 1.0){
                std::complex<double> r = z[i];
                std::complex<double> inv = 1.0/(std::complex<double>(1.0,0.0) - r);
                std::vector<std::complex<double>> nh(ch.size()+1, std::complex<double>(0.0,0.0));
                for (size_t a=0;a<ch.size();a++){
                    nh[a]   += ch[a]*(-r)*inv;
                    nh[a+1] += ch[a]*inv;
                }
                ch.swap(nh);
            }
        }
    }
    double s2 = std::sqrt(2.0);
    for (int i=0;i<L && i<(int)ch.size() && i<LF;i++) h20[i] = ch[i].real()*s2;
}
static Filters make_filters(){
    Filters F;
    for (int e=0;e<NE;e++){
        int N = e+1, L = 2*N;
        double h[LF];
        db_lo(N, h);
        for (int tp=0;tp<LF;tp++){
            F.f[e][0][tp] = (float)h[tp];
            F.f[e][1][tp] = (tp < L) ? (float)(h[L-1-tp] * ((tp&1)?-1.0:1.0)) : 0.f;
        }
    }
    return F;
}

// ---------------- launch ----------------
extern "C" void kernel_launch(void* const* d_in, const int* in_sizes, int n_in,
                              void* d_out, int out_size){
    const float* x     = (const float*)d_in[0];
    const float* label = (const float*)d_in[1];
    const float* fc0_w = (const float*)d_in[2];
    const float* fc0_b = (const float*)d_in[3];
    const float* fc1_w = (const float*)d_in[4];
    const float* fc1_b = (const float*)d_in[5];
    const float* gwl   = (const float*)d_in[6];
    const float* gbl   = (const float*)d_in[7];
    const float* gwg   = (const float*)d_in[8];
    const float* gbg   = (const float*)d_in[9];
    const float* ew1   = (const float*)d_in[10];
    const float* ew2   = (const float*)d_in[11];
    const float* ww    = (const float*)d_in[12];
    const float* wb    = (const float*)d_in[13];
    const float* fc2_w = (const float*)d_in[14];
    const float* fc2_b = (const float*)d_in[15];
    const float* fc3_w = (const float*)d_in[16];
    const float* fc3_b = (const float*)d_in[17];

    Filters F = make_filters();

    float *dA, *dB, *dCorr, *dCoefT;
    __half *dHhi,*dHlo,*dDhi,*dDlo,*dStH,*dSxH;
    cudaGetSymbolAddress((void**)&dA,    g_bufA);
    cudaGetSymbolAddress((void**)&dB,    g_bufB);
    cudaGetSymbolAddress((void**)&dCorr, g_corr);
    cudaGetSymbolAddress((void**)&dCoefT,g_coefT);
    cudaGetSymbolAddress((void**)&dHhi,  g_Hhi);
    cudaGetSymbolAddress((void**)&dHlo,  g_Hlo);
    cudaGetSymbolAddress((void**)&dDhi,  g_Dhi);
    cudaGetSymbolAddress((void**)&dDlo,  g_Dlo);
    cudaGetSymbolAddress((void**)&dStH,  g_StH);
    cudaGetSymbolAddress((void**)&dSxH,  g_SxH);

    cudaFuncSetAttribute(gemm_kernel<0>, cudaFuncAttributeMaxDynamicSharedMemorySize, GEMM_SMEM);
    cudaFuncSetAttribute(gemm_kernel<1>, cudaFuncAttributeMaxDynamicSharedMemorySize, GEMM_SMEM);

    // launch order puts first gemm at slot 6 so ncu (-s 5 -c 1) profiles it
    build_syn_kernel<<<NE*2*NM, 128>>>(F);                              // 1
    transw_kernel<<<dim3(64, NHID*NE), 256>>>(ew1, ew2);                // 2
    prep_lift_kernel<<<1, 64>>>(fc0_w, fc0_b, fc1_w, fc1_b);            // 3
    lift_kernel<<<(NROW*NS/4+255)/256, 256>>>(x);                       // 4
    xf_kernel<<<NROW, 256>>>(dA);                                       // 5
    gemm_kernel<1><<<dim3(NCOL/128, NROW/128), 256, GEMM_SMEM>>>(       // 6  <- profiled
        dHhi, dHlo, dStH, dCoefT, NROW, NCOL, NS);
    gate_kernel<<<1, 256>>>(label, gwl, gbl, gwg, gbg);                 // 7

    float* cur = dA; float* nxt = dB;
    for (int hd=0; hd<NHID; hd++){
        if (hd > 0){
            gemm_kernel<1><<<dim3(NCOL/128, NROW/128), 256, GEMM_SMEM>>>(
                dHhi, dHlo, dStH, dCoefT, NROW, NCOL, NS);
        }
        mix_kernel<<<dim3(NM, NE), 256>>>(hd);
        tsplit_kernel<<<dim3(NCOL/32, NROW/32), 256>>>();
        gemm_kernel<0><<<dim3(NS/128, NROW/128), 256, GEMM_SMEM>>>(
            dDhi, dDlo, dSxH, dCorr, NROW, NS, NCOL);
        combine_kernel<<<dim3(NS/64, NB), 256>>>(cur, dCorr, ww, wb, nxt, hd);
        float* tp = cur; cur = nxt; nxt = tp;
    }
    head_kernel<<<dim3(NS/8, NB), 256>>>(cur, fc2_w, fc2_b, fc3_w, fc3_b, (float*)d_out);
}